// round 11
// baseline (speedup 1.0000x reference)
#include <cuda_runtime.h>
#include <cuda_bf16.h>
#include <cstdint>

#define NE 8
#define NT 4096
#define DH 2048
#define DI 5632
#define NR 128
#define PITCH 80          // bytes per 32-bf16 smem row (conflict-free for LDSM)
#define ABUF 10240        // 128 rows * 80B
#define BBUF 10240
#define BBUF2 5120        // 64 rows * 80B

// ===================== low-level helpers ====================================
__device__ __forceinline__ uint32_t smem_u32(const void* p) {
    uint32_t a;
    asm("{ .reg .u64 t; cvta.to.shared.u64 t, %1; cvt.u32.u64 %0, t; }"
        : "=r"(a) : "l"(p));
    return a;
}
#define CP16(dst, src) \
    asm volatile("cp.async.cg.shared.global [%0], [%1], 16;" \
                 :: "r"(dst), "l"(src) : "memory")
#define CPCOMMIT() asm volatile("cp.async.commit_group;" ::: "memory")
#define CPWAIT(n)  asm volatile("cp.async.wait_group %0;" :: "n"(n) : "memory")

__device__ __forceinline__ void ldsm4(uint32_t r[4], uint32_t addr) {
    asm volatile("ldmatrix.sync.aligned.m8n8.x4.shared.b16 {%0,%1,%2,%3}, [%4];"
        : "=r"(r[0]), "=r"(r[1]), "=r"(r[2]), "=r"(r[3]) : "r"(addr));
}

__device__ __forceinline__ void mma_bf16(
    float c[4], const uint32_t a[4], const uint32_t b[2])
{
    asm volatile(
        "mma.sync.aligned.m16n8k16.row.col.f32.bf16.bf16.f32 "
        "{%0,%1,%2,%3}, {%4,%5,%6,%7}, {%8,%9}, {%0,%1,%2,%3};"
        : "+f"(c[0]), "+f"(c[1]), "+f"(c[2]), "+f"(c[3])
        : "r"(a[0]), "r"(a[1]), "r"(a[2]), "r"(a[3]),
          "r"(b[0]), "r"(b[1]));
}

// ===================== scratch globals ======================================
__device__ int g_offsets[NE + 1];
__device__ int g_perm[NT];

__device__ __nv_bfloat16 g_Xb [NT * DH];
__device__ __nv_bfloat16 g_W1 [NE * 256 * DH];  // rows 0..127 gate_A, 128..255 up_A
__device__ __nv_bfloat16 g_Ad [NE * NR * DI];
__device__ __nv_bfloat16 g_Bg [NE * DI * NR];   // folded: gate_B @ gate_C
__device__ __nv_bfloat16 g_Bu [NE * DI * NR];   // folded: up_B @ up_C
__device__ __nv_bfloat16 g_Bd [NE * DH * NR];   // folded: down_B @ down_C
__device__ __nv_bfloat16 g_CgT[NR * NR];        // gate_C^T
__device__ __nv_bfloat16 g_CuT[NR * NR];
__device__ __nv_bfloat16 g_CdT[NR * NR];
__device__ __nv_bfloat16 g_H  [NT * 256];
__device__ __nv_bfloat16 g_Y  [NT * DI];
__device__ __nv_bfloat16 g_Hd [NT * NR];
__device__ float g_P1[4 * NT * 256];
__device__ float g_P3[8 * NT * NR];

// ===================== single-block permutation =============================
__global__ void k_perm(const int* __restrict__ idx) {
    __shared__ int cnt[NE], off[NE], cur[NE];
    int tid = threadIdx.x;
    if (tid < NE) { cnt[tid] = 0; cur[tid] = 0; }
    __syncthreads();
    for (int t = tid; t < NT; t += 1024) atomicAdd(&cnt[idx[t]], 1);
    __syncthreads();
    if (tid == 0) {
        int s = 0;
        for (int e = 0; e < NE; ++e) { off[e] = s; g_offsets[e] = s; s += cnt[e]; }
        g_offsets[NE] = s;
    }
    __syncthreads();
    for (int t = tid; t < NT; t += 1024) {
        int e = idx[t];
        int p = atomicAdd(&cur[e], 1);
        g_perm[off[e] + p] = t;
    }
}

// ===================== one-shot conversion kernel ===========================
__device__ __forceinline__ uint2 cvt4(float4 v) {
    __nv_bfloat162 lo = __floats2bfloat162_rn(v.x, v.y);
    __nv_bfloat162 hi = __floats2bfloat162_rn(v.z, v.w);
    uint2 o; o.x = *(uint32_t*)&lo; o.y = *(uint32_t*)&hi;
    return o;
}

#define R0N (NT * DH / 4)
#define RA1 (NE * 128 * DH / 4)
#define RA3 (NE * NR * DI / 4)
#define RCT (NR * NR)

__global__ void conv_all(
    const float* __restrict__ x,
    const float* __restrict__ gate_A, const float* __restrict__ up_A,
    const float* __restrict__ down_A,
    const float* __restrict__ gate_C, const float* __restrict__ up_C,
    const float* __restrict__ down_C,
    __nv_bfloat16* __restrict__ Xb, __nv_bfloat16* __restrict__ W1,
    __nv_bfloat16* __restrict__ Ad,
    __nv_bfloat16* __restrict__ CgT, __nv_bfloat16* __restrict__ CuT,
    __nv_bfloat16* __restrict__ CdT)
{
    int r = blockIdx.y;
    int stride = gridDim.x * 256;
    int i0 = blockIdx.x * 256 + threadIdx.x;
    if (r == 0) {
        for (int i = i0; i < R0N; i += stride)
            ((uint2*)Xb)[i] = cvt4(((const float4*)x)[i]);
    } else if (r == 1) {
        for (int i = i0; i < RA1; i += stride) {
            int e = i / (128 * DH / 4), off = i % (128 * DH / 4);
            *(uint2*)(W1 + (size_t)e * 256 * DH + (size_t)off * 4) =
                cvt4(((const float4*)gate_A)[i]);
        }
    } else if (r == 2) {
        for (int i = i0; i < RA1; i += stride) {
            int e = i / (128 * DH / 4), off = i % (128 * DH / 4);
            *(uint2*)(W1 + (size_t)e * 256 * DH + (size_t)128 * DH + (size_t)off * 4) =
                cvt4(((const float4*)up_A)[i]);
        }
    } else if (r == 3) {
        for (int i = i0; i < RA3; i += stride)
            ((uint2*)Ad)[i] = cvt4(((const float4*)down_A)[i]);
    } else if (r == 4) {
        for (int i = i0; i < RCT; i += stride) {
            int s = i >> 7, rr = i & 127;
            CgT[rr * NR + s] = __float2bfloat16(gate_C[s * NR + rr]);
            CuT[rr * NR + s] = __float2bfloat16(up_C[s * NR + rr]);
        }
    } else {
        for (int i = i0; i < RCT; i += stride) {
            int s = i >> 7, rr = i & 127;
            CdT[rr * NR + s] = __float2bfloat16(down_C[s * NR + rr]);
        }
    }
}

// ===================== fused convert+fold kernel ============================
__global__ void __launch_bounds__(256) fold_b(
    const float* __restrict__ gate_B, const float* __restrict__ up_B,
    const float* __restrict__ down_B,
    const __nv_bfloat16* __restrict__ CgT, const __nv_bfloat16* __restrict__ CuT,
    const __nv_bfloat16* __restrict__ CdT,
    __nv_bfloat16* __restrict__ Bg, __nv_bfloat16* __restrict__ Bu,
    __nv_bfloat16* __restrict__ Bd)
{
    extern __shared__ char dsm[];
    uint32_t sb = smem_u32(dsm);
    uint32_t sA = sb, sC = sb + 4 * ABUF;
    char* pA = dsm;
    char* pC = dsm + 4 * ABUF;

    int z = blockIdx.x;
    int e = z / 104, w = z % 104;
    const float* src;
    const __nv_bfloat16* CT;
    __nv_bfloat16* dst;
    int row0;
    if (w < 44)      { src = gate_B + (size_t)e * DI * NR; CT = CgT; dst = g_Bg + (size_t)e * DI * NR; row0 = w * 128; }
    else if (w < 88) { src = up_B   + (size_t)e * DI * NR; CT = CuT; dst = g_Bu + (size_t)e * DI * NR; row0 = (w - 44) * 128; }
    else             { src = down_B + (size_t)e * DH * NR; CT = CdT; dst = g_Bd + (size_t)e * DH * NR; row0 = (w - 88) * 128; }
    (void)Bg; (void)Bu; (void)Bd;

    int tid = threadIdx.x;

    #pragma unroll
    for (int l = 0; l < 16; ++l) {
        int idx = tid + l * 256;
        int n = idx >> 5;
        int c4 = idx & 31;
        int col = c4 * 4;
        float4 v = *(const float4*)&src[(size_t)(row0 + n) * NR + col];
        int buf = col >> 5;
        int boff = (col & 31) * 2;
        *(uint2*)(pA + buf * ABUF + n * PITCH + boff) = cvt4(v);
    }
    #pragma unroll
    for (int l = 0; l < 8; ++l) {
        int idx = tid + l * 256;
        int r = idx >> 4;
        int ch = idx & 15;
        int scol = ch * 8;
        uint4 v = *(const uint4*)&CT[r * NR + scol];
        int buf = scol >> 5;
        int boff = (scol & 31) * 2;
        *(uint4*)(pC + buf * ABUF + r * PITCH + boff) = v;
    }
    __syncthreads();

    int lane = tid & 31, wid = tid >> 5;
    int wm = wid >> 1, wn = wid & 1;
    int gq = lane >> 2, tig = lane & 3;
    int l7 = lane & 7, lb3 = (lane >> 3) & 1, lb4 = (lane >> 4) & 1;

    uint32_t aLane = sA + (uint32_t)(wm * 32 + l7 + lb3 * 8) * PITCH + lb4 * 16;
    uint32_t bLane = sC + (uint32_t)(wn * 64 + l7 + lb4 * 8) * PITCH + lb3 * 16;

    float acc[2][8][4];
    #pragma unroll
    for (int mt = 0; mt < 2; ++mt)
        #pragma unroll
        for (int nt = 0; nt < 8; ++nt)
            #pragma unroll
            for (int j = 0; j < 4; ++j) acc[mt][nt][j] = 0.f;

    #pragma unroll
    for (int buf = 0; buf < 4; ++buf) {
        #pragma unroll
        for (int ks = 0; ks < 2; ++ks) {
            uint32_t a[2][4], b[8][2];
            uint32_t ab = aLane + buf * ABUF + ks * 32;
            #pragma unroll
            for (int mt = 0; mt < 2; ++mt)
                ldsm4(a[mt], ab + mt * 16 * PITCH);
            uint32_t bb = bLane + buf * ABUF + ks * 32;
            #pragma unroll
            for (int p = 0; p < 4; ++p) {
                uint32_t q[4];
                ldsm4(q, bb + p * 16 * PITCH);
                b[2 * p][0] = q[0]; b[2 * p][1] = q[1];
                b[2 * p + 1][0] = q[2]; b[2 * p + 1][1] = q[3];
            }
            #pragma unroll
            for (int mt = 0; mt < 2; ++mt)
                #pragma unroll
                for (int nt = 0; nt < 8; ++nt)
                    mma_bf16(acc[mt][nt], a[mt], b[nt]);
        }
    }

    #pragma unroll
    for (int mt = 0; mt < 2; ++mt) {
        #pragma unroll
        for (int half = 0; half < 2; ++half) {
            int r = wm * 32 + mt * 16 + half * 8 + gq;
            size_t rowoff = (size_t)(row0 + r) * NR;
            #pragma unroll
            for (int nt = 0; nt < 8; ++nt) {
                int cc = wn * 64 + nt * 8 + 2 * tig;
                __nv_bfloat162 o = __floats2bfloat162_rn(
                    acc[mt][nt][half * 2 + 0], acc[mt][nt][half * 2 + 1]);
                *(uint32_t*)&dst[rowoff + cc] = *(uint32_t*)&o;
            }
        }
    }
}

// ===================== bf16 MMA GEMM (3-stage, single sync/iter) ============
// D[i][n] = sum_k A[i][k] * B[n][k].  BM=128, BN=128, BK=32.
// EPI 0: fp32 store (+split offset). EPI 2: fp32 +bias +perm scatter. EPI 3: bf16.
template<bool GATHER, bool WEIGHTS, int EPI, int SPLITK>
__global__ void __launch_bounds__(256, 2) mma1(
    const __nv_bfloat16* __restrict__ A, int lda, size_t strideAe, int Mtot,
    const __nv_bfloat16* __restrict__ B, int ldb, size_t strideBe, int Ktot,
    void* __restrict__ outp, int ldc, size_t splitStride,
    const float* __restrict__ bias)
{
    extern __shared__ char dsm[];
    uint32_t sb = smem_u32(dsm);
    uint32_t sA = sb, sB = sb + 3 * ABUF;
    int* rows = (int*)(dsm + 6 * ABUF);

    int z = blockIdx.z;
    int e, base, iend;
    if (WEIGHTS) { e = z; base = 0; iend = Mtot; }
    else {
        e = z / SPLITK;
        base = g_offsets[e]; iend = g_offsets[e + 1];
    }
    int sk = WEIGHTS ? 0 : (z % SPLITK);
    int i0 = base + blockIdx.y * 128;
    if (i0 >= iend) return;
    int nb = blockIdx.x * 128;
    int tid = threadIdx.x;

    if (tid < 128) {
        int i = i0 + tid; if (i >= iend) i = iend - 1;
        rows[tid] = GATHER ? g_perm[i] : i;
    }
    __syncthreads();

    const __nv_bfloat16* Ap = A + (WEIGHTS ? (size_t)e * strideAe : 0);
    const __nv_bfloat16* Bp = B + (size_t)e * strideBe;

    int kstep = Ktot / SPLITK;
    int kbeg  = sk * kstep;
    int nk    = kstep / 32;

    int lane = tid & 31, wid = tid >> 5;
    int wm = wid >> 1, wn = wid & 1;
    int gq = lane >> 2, tig = lane & 3;
    int l7 = lane & 7, lb3 = (lane >> 3) & 1, lb4 = (lane >> 4) & 1;

    uint32_t aLane = sA + (uint32_t)(wm * 32 + l7 + lb3 * 8) * PITCH + lb4 * 16;
    uint32_t bLane = sB + (uint32_t)(wn * 64 + l7 + lb4 * 8) * PITCH + lb3 * 16;

    float acc[2][8][4];
    #pragma unroll
    for (int mt = 0; mt < 2; ++mt)
        #pragma unroll
        for (int nt = 0; nt < 8; ++nt)
            #pragma unroll
            for (int j = 0; j < 4; ++j) acc[mt][nt][j] = 0.f;

    auto stage = [&](int tile, int bufi) {
        int kb = kbeg + tile * 32;
        #pragma unroll
        for (int l = 0; l < 2; ++l) {
            int idx = tid + l * 256;
            int r = idx >> 2, ch = idx & 3;
            CP16(sA + bufi * ABUF + r * PITCH + ch * 16,
                 Ap + (size_t)rows[r] * lda + kb + ch * 8);
        }
        #pragma unroll
        for (int l = 0; l < 2; ++l) {
            int idx = tid + l * 256;
            int n = idx >> 2, ch = idx & 3;
            CP16(sB + bufi * ABUF + n * PITCH + ch * 16,
                 Bp + (size_t)(nb + n) * ldb + kb + ch * 8);
        }
        CPCOMMIT();
    };

    // prologue: stage tiles 0, 1
    stage(0, 0);
    if (nk > 1) stage(1, 1);

    int bcur = 0;   // buffer of tile t
    int bstg = 2;   // buffer for tile t+2
    for (int t = 0; t < nk; ++t) {
        if (t < nk - 1) { CPWAIT(1); } else { CPWAIT(0); }
        __syncthreads();
        if (t + 2 < nk) stage(t + 2, bstg);

        uint32_t abase = aLane + bcur * ABUF;
        uint32_t bbase = bLane + bcur * ABUF;
        #pragma unroll
        for (int ks = 0; ks < 2; ++ks) {
            uint32_t a[2][4], b[8][2];
            uint32_t ab = abase + ks * 32;
            #pragma unroll
            for (int mt = 0; mt < 2; ++mt)
                ldsm4(a[mt], ab + mt * 16 * PITCH);
            uint32_t bb = bbase + ks * 32;
            #pragma unroll
            for (int p = 0; p < 4; ++p) {
                uint32_t q[4];
                ldsm4(q, bb + p * 16 * PITCH);
                b[2 * p][0] = q[0]; b[2 * p][1] = q[1];
                b[2 * p + 1][0] = q[2]; b[2 * p + 1][1] = q[3];
            }
            #pragma unroll
            for (int mt = 0; mt < 2; ++mt)
                #pragma unroll
                for (int nt = 0; nt < 8; ++nt)
                    mma_bf16(acc[mt][nt], a[mt], b[nt]);
        }
        bcur = (bcur == 2) ? 0 : bcur + 1;
        bstg = (bstg == 2) ? 0 : bstg + 1;
    }

    // epilogue
    float* Cf = (float*)outp;
    __nv_bfloat16* Cb = (__nv_bfloat16*)outp;
    if (EPI == 0) Cf += (size_t)sk * splitStride;
    if (EPI == 3 && WEIGHTS) Cb += (size_t)e * (size_t)Mtot * ldc;

    #pragma unroll
    for (int mt = 0; mt < 2; ++mt) {
        #pragma unroll
        for (int half = 0; half < 2; ++half) {
            int r = wm * 32 + mt * 16 + half * 8 + gq;
            int gi = i0 + r;
            if (gi >= iend) continue;
            int orow = (EPI == 2) ? g_perm[gi] : gi;
            size_t rowoff = (size_t)orow * ldc + nb;
            #pragma unroll
            for (int nt = 0; nt < 8; ++nt) {
                int cc = wn * 64 + nt * 8 + 2 * tig;
                float v0 = acc[mt][nt][half * 2 + 0];
                float v1 = acc[mt][nt][half * 2 + 1];
                if (EPI == 0) {
                    *(float2*)&Cf[rowoff + cc] = make_float2(v0, v1);
                } else if (EPI == 2) {
                    const float* bp = bias + (size_t)e * DH + nb + cc;
                    *(float2*)&Cf[rowoff + cc] = make_float2(v0 + bp[0], v1 + bp[1]);
                } else {
                    __nv_bfloat162 o = __floats2bfloat162_rn(v0, v1);
                    *(uint32_t*)&Cb[rowoff + cc] = *(uint32_t*)&o;
                }
            }
        }
    }
}

// ===================== fused gate/up GEMM + SwiGLU (S=2, proven) ============
__global__ void __launch_bounds__(256, 2) mma2(
    const __nv_bfloat16* __restrict__ H2,
    const __nv_bfloat16* __restrict__ Bgw, const __nv_bfloat16* __restrict__ Buw,
    __nv_bfloat16* __restrict__ Y)
{
    extern __shared__ char dsm[];
    uint32_t sb = smem_u32(dsm);
    uint32_t sAg = sb, sAu = sb + 2 * ABUF;
    uint32_t sBg = sb + 4 * ABUF, sBu = sb + 4 * ABUF + 2 * BBUF2;

    int e = blockIdx.z;
    int base = g_offsets[e], iend = g_offsets[e + 1];
    int i0 = base + blockIdx.y * 128;
    if (i0 >= iend) return;
    int nb = blockIdx.x * 64;
    int tid = threadIdx.x;

    const __nv_bfloat16* Bg = Bgw + (size_t)e * DI * NR;
    const __nv_bfloat16* Bu = Buw + (size_t)e * DI * NR;

    int lane = tid & 31, wid = tid >> 5;
    int wm = wid >> 1, wn = wid & 1;
    int gq = lane >> 2, tig = lane & 3;
    int l7 = lane & 7, lb3 = (lane >> 3) & 1, lb4 = (lane >> 4) & 1;

    uint32_t aOffL = (uint32_t)(wm * 32 + l7 + lb3 * 8) * PITCH + lb4 * 16;
    uint32_t bOffL = (uint32_t)(wn * 32 + l7 + lb4 * 8) * PITCH + lb3 * 16;

    float accG[2][4][4], accU[2][4][4];
    #pragma unroll
    for (int mt = 0; mt < 2; ++mt)
        #pragma unroll
        for (int nt = 0; nt < 4; ++nt)
            #pragma unroll
            for (int j = 0; j < 4; ++j) { accG[mt][nt][j] = 0.f; accU[mt][nt][j] = 0.f; }

    const int nk = 4;
    auto rowOf = [&](int r) { int i = i0 + r; return (i < iend) ? i : (iend - 1); };

    {
        #pragma unroll
        for (int l = 0; l < 4; ++l) {
            int idx = tid + l * 256;
            int st = idx >> 9, rr = (idx >> 2) & 127, ch = idx & 3;
            uint32_t dst = (st ? sAu : sAg) + rr * PITCH + ch * 16;
            CP16(dst, H2 + (size_t)rowOf(rr) * 256 + st * 128 + 0 + ch * 8);
        }
        #pragma unroll
        for (int l = 0; l < 2; ++l) {
            int idx = tid + l * 256;
            int st = idx >> 8, n = (idx >> 2) & 63, ch = idx & 3;
            const __nv_bfloat16* src = (st ? Bu : Bg) + (size_t)(nb + n) * NR + 0 + ch * 8;
            uint32_t dst = (st ? sBu : sBg) + n * PITCH + ch * 16;
            CP16(dst, src);
        }
        CPCOMMIT();
    }

    for (int t = 0; t < nk; ++t) {
        int buf = t & 1;
        if (t + 1 < nk) {
            int kb = (t + 1) * 32;
            int nbuf = buf ^ 1;
            #pragma unroll
            for (int l = 0; l < 4; ++l) {
                int idx = tid + l * 256;
                int st = idx >> 9, rr = (idx >> 2) & 127, ch = idx & 3;
                uint32_t dst = (st ? sAu : sAg) + nbuf * ABUF + rr * PITCH + ch * 16;
                CP16(dst, H2 + (size_t)rowOf(rr) * 256 + st * 128 + kb + ch * 8);
            }
            #pragma unroll
            for (int l = 0; l < 2; ++l) {
                int idx = tid + l * 256;
                int st = idx >> 8, n = (idx >> 2) & 63, ch = idx & 3;
                const __nv_bfloat16* src = (st ? Bu : Bg) + (size_t)(nb + n) * NR + kb + ch * 8;
                uint32_t dst = (st ? sBu : sBg) + nbuf * BBUF2 + n * PITCH + ch * 16;
                CP16(dst, src);
            }
            CPCOMMIT();
            CPWAIT(1);
        } else {
            CPWAIT(0);
        }
        __syncthreads();

        #pragma unroll
        for (int ks = 0; ks < 2; ++ks) {
            uint32_t ag[2][4], au[2][4], bg[4][2], bu[4][2];
            uint32_t abg = sAg + buf * ABUF + aOffL + ks * 32;
            uint32_t abu = sAu + buf * ABUF + aOffL + ks * 32;
            #pragma unroll
            for (int mt = 0; mt < 2; ++mt) {
                ldsm4(ag[mt], abg + mt * 16 * PITCH);
                ldsm4(au[mt], abu + mt * 16 * PITCH);
            }
            uint32_t bbg = sBg + buf * BBUF2 + bOffL + ks * 32;
            uint32_t bbu = sBu + buf * BBUF2 + bOffL + ks * 32;
            #pragma unroll
            for (int p = 0; p < 2; ++p) {
                uint32_t qg[4], qu[4];
                ldsm4(qg, bbg + p * 16 * PITCH);
                ldsm4(qu, bbu + p * 16 * PITCH);
                bg[2 * p][0] = qg[0]; bg[2 * p][1] = qg[1];
                bg[2 * p + 1][0] = qg[2]; bg[2 * p + 1][1] = qg[3];
                bu[2 * p][0] = qu[0]; bu[2 * p][1] = qu[1];
                bu[2 * p + 1][0] = qu[2]; bu[2 * p + 1][1] = qu[3];
            }
            #pragma unroll
            for (int mt = 0; mt < 2; ++mt)
                #pragma unroll
                for (int nt = 0; nt < 4; ++nt) {
                    mma_bf16(accG[mt][nt], ag[mt], bg[nt]);
                    mma_bf16(accU[mt][nt], au[mt], bu[nt]);
                }
        }
        __syncthreads();
    }

    #pragma unroll
    for (int mt = 0; mt < 2; ++mt) {
        #pragma unroll
        for (int half = 0; half < 2; ++half) {
            int r = wm * 32 + mt * 16 + half * 8 + gq;
            int gi = i0 + r;
            if (gi >= iend) continue;
            size_t rowoff = (size_t)gi * DI + nb;
            #pragma unroll
            for (int nt = 0; nt < 4; ++nt) {
                int cc = wn * 32 + nt * 8 + 2 * tig;
                float g0 = accG[mt][nt][half * 2 + 0];
                float g1 = accG[mt][nt][half * 2 + 1];
                float u0 = accU[mt][nt][half * 2 + 0];
                float u1 = accU[mt][nt][half * 2 + 1];
                float y0 = u0 * g0 / (1.f + __expf(-g0));
                float y1 = u1 * g1 / (1.f + __expf(-g1));
                __nv_bfloat162 o = __floats2bfloat162_rn(y0, y1);
                *(uint32_t*)&Y[rowoff + cc] = *(uint32_t*)&o;
            }
        }
    }
}

// ===================== split-K reduce -> bf16 ================================
template<int SR>
__global__ void reduce_bf(const float4* __restrict__ P, uint2* __restrict__ O,
                          int n4, size_t stride4)
{
    int i = blockIdx.x * 256 + threadIdx.x;
    if (i >= n4) return;
    float4 s = P[i];
    #pragma unroll
    for (int k = 1; k < SR; ++k) {
        float4 v = P[(size_t)k * stride4 + i];
        s.x += v.x; s.y += v.y; s.z += v.z; s.w += v.w;
    }
    __nv_bfloat162 lo = __floats2bfloat162_rn(s.x, s.y);
    __nv_bfloat162 hi = __floats2bfloat162_rn(s.z, s.w);
    uint2 o; o.x = *(uint32_t*)&lo; o.y = *(uint32_t*)&hi;
    O[i] = o;
}

// ===================== launch ================================================
extern "C" void kernel_launch(void* const* d_in, const int* in_sizes, int n_in,
                              void* d_out, int out_size)
{
    const float* x         = (const float*)d_in[0];
    const int*   eidx      = (const int*)  d_in[1];
    const float* gate_A    = (const float*)d_in[2];
    const float* gate_C    = (const float*)d_in[3];
    const float* gate_B    = (const float*)d_in[4];
    const float* up_A      = (const float*)d_in[5];
    const float* up_C      = (const float*)d_in[6];
    const float* up_B      = (const float*)d_in[7];
    const float* down_A    = (const float*)d_in[8];
    const float* down_C    = (const float*)d_in[9];
    const float* down_B    = (const float*)d_in[10];
    const float* down_bias = (const float*)d_in[11];
    float* out = (float*)d_out;

    __nv_bfloat16 *pXb, *pW1, *pAd, *pBg, *pBu, *pBd, *pCgT, *pCuT, *pCdT,
                  *pH, *pY, *pHd;
    float *pP1, *pP3;
    cudaGetSymbolAddress((void**)&pXb,  g_Xb);
    cudaGetSymbolAddress((void**)&pW1,  g_W1);
    cudaGetSymbolAddress((void**)&pAd,  g_Ad);
    cudaGetSymbolAddress((void**)&pBg,  g_Bg);
    cudaGetSymbolAddress((void**)&pBu,  g_Bu);
    cudaGetSymbolAddress((void**)&pBd,  g_Bd);
    cudaGetSymbolAddress((void**)&pCgT, g_CgT);
    cudaGetSymbolAddress((void**)&pCuT, g_CuT);
    cudaGetSymbolAddress((void**)&pCdT, g_CdT);
    cudaGetSymbolAddress((void**)&pH,   g_H);
    cudaGetSymbolAddress((void**)&pY,   g_Y);
    cudaGetSymbolAddress((void**)&pHd,  g_Hd);
    cudaGetSymbolAddress((void**)&pP1,  g_P1);
    cudaGetSymbolAddress((void**)&pP3,  g_P3);

    const int SM1 = 6 * ABUF + 1024;               // 62464 (3-stage, 2 CTAs/SM)
    const int SM2 = 4 * ABUF + 4 * BBUF2 + 512;    // 61952
    const int SMF = 8 * ABUF;                      // 81920
    cudaFuncSetAttribute(mma1<true,  false, 0, 4>, cudaFuncAttributeMaxDynamicSharedMemorySize, SM1);
    cudaFuncSetAttribute(mma1<false, false, 0, 4>, cudaFuncAttributeMaxDynamicSharedMemorySize, SM1);
    cudaFuncSetAttribute(mma1<false, false, 2, 1>, cudaFuncAttributeMaxDynamicSharedMemorySize, SM1);
    cudaFuncSetAttribute(mma2, cudaFuncAttributeMaxDynamicSharedMemorySize, SM2);
    cudaFuncSetAttribute(fold_b, cudaFuncAttributeMaxDynamicSharedMemorySize, SMF);

    // permutation (1) + conversions/transposes (1) + fused folds (1)
    k_perm<<<1, 1024>>>(eidx);
    conv_all<<<dim3(1024, 6), 256>>>(
        x, gate_A, up_A, down_A, gate_C, up_C, down_C,
        pXb, pW1, pAd, pCgT, pCuT, pCdT);
    fold_b<<<NE * 104, 256, SMF>>>(
        gate_B, up_B, down_B, pCgT, pCuT, pCdT, pBg, pBu, pBd);

    // K1: H = x_perm @ [gate_A; up_A]^T   (split-K 4, fp32 partials)
    mma1<true, false, 0, 4><<<dim3(2, NT / 128, NE * 4), 256, SM1>>>(
        pXb, DH, 0, 0, pW1, DH, (size_t)256 * DH, DH,
        pP1, 256, (size_t)NT * 256, nullptr);
    reduce_bf<4><<<(NT * 256 / 4 + 255) / 256, 256>>>(
        (const float4*)pP1, (uint2*)pH, NT * 256 / 4, (size_t)NT * 256 / 4);

    // K2: Y = silu(Hg @ Bg'^T) * (Hu @ Bu'^T)
    mma2<<<dim3(DI / 64, NT / 128, NE), 256, SM2>>>(pH, pBg, pBu, pY);

    // K3: Hd = Y @ down_A^T   (split-K 4)
    mma1<false, false, 0, 4><<<dim3(1, NT / 128, NE * 4), 256, SM1>>>(
        pY, DI, 0, 0, pAd, DI, (size_t)NR * DI, DI,
        pP3, NR, (size_t)NT * NR, nullptr);
    reduce_bf<4><<<(NT * NR / 4 + 255) / 256, 256>>>(
        (const float4*)pP3, (uint2*)pHd, NT * NR / 4, (size_t)NT * NR / 4);

    // K4: out[perm[i],:] = Hd @ Bd'^T + bias[e]
    mma1<false, false, 2, 1><<<dim3(DH / 128, NT / 128, NE), 256, SM1>>>(
        pHd, NR, 0, 0, pBd, NR, (size_t)DH * NR, NR,
        out, DH, 0, down_bias);
}

// round 12
// speedup vs baseline: 1.0223x; 1.0223x over previous
#include <cuda_runtime.h>
#include <cuda_bf16.h>
#include <cstdint>

#define NE 8
#define NT 4096
#define DH 2048
#define DI 5632
#define NR 128
#define PITCH 80          // bytes per 32-bf16 smem row (conflict-free for LDSM)
#define ABUF 10240        // 128 rows * 80B
#define BBUF 10240
#define BBUF2 5120        // 64 rows * 80B

// ===================== low-level helpers ====================================
__device__ __forceinline__ uint32_t smem_u32(const void* p) {
    uint32_t a;
    asm("{ .reg .u64 t; cvta.to.shared.u64 t, %1; cvt.u32.u64 %0, t; }"
        : "=r"(a) : "l"(p));
    return a;
}
#define CP16(dst, src) \
    asm volatile("cp.async.cg.shared.global [%0], [%1], 16;" \
                 :: "r"(dst), "l"(src) : "memory")
#define CPCOMMIT() asm volatile("cp.async.commit_group;" ::: "memory")
#define CPWAIT(n)  asm volatile("cp.async.wait_group %0;" :: "n"(n) : "memory")

__device__ __forceinline__ void ldsm4(uint32_t r[4], uint32_t addr) {
    asm volatile("ldmatrix.sync.aligned.m8n8.x4.shared.b16 {%0,%1,%2,%3}, [%4];"
        : "=r"(r[0]), "=r"(r[1]), "=r"(r[2]), "=r"(r[3]) : "r"(addr));
}

__device__ __forceinline__ void mma_bf16(
    float c[4], const uint32_t a[4], const uint32_t b[2])
{
    asm volatile(
        "mma.sync.aligned.m16n8k16.row.col.f32.bf16.bf16.f32 "
        "{%0,%1,%2,%3}, {%4,%5,%6,%7}, {%8,%9}, {%0,%1,%2,%3};"
        : "+f"(c[0]), "+f"(c[1]), "+f"(c[2]), "+f"(c[3])
        : "r"(a[0]), "r"(a[1]), "r"(a[2]), "r"(a[3]),
          "r"(b[0]), "r"(b[1]));
}

// ===================== scratch globals ======================================
__device__ int g_offsets[NE + 1];
__device__ int g_perm[NT];

__device__ __nv_bfloat16 g_Xb [NT * DH];
__device__ __nv_bfloat16 g_W1 [NE * 256 * DH];  // rows 0..127 gate_A, 128..255 up_A
__device__ __nv_bfloat16 g_Ad [NE * NR * DI];
__device__ __nv_bfloat16 g_Bg [NE * DI * NR];   // folded: gate_B @ gate_C
__device__ __nv_bfloat16 g_Bu [NE * DI * NR];   // folded: up_B @ up_C
__device__ __nv_bfloat16 g_Bd [NE * DH * NR];   // folded: down_B @ down_C
__device__ __nv_bfloat16 g_CgT[NR * NR];        // gate_C^T
__device__ __nv_bfloat16 g_CuT[NR * NR];
__device__ __nv_bfloat16 g_CdT[NR * NR];
__device__ __nv_bfloat16 g_H  [NT * 256];
__device__ __nv_bfloat16 g_Y  [NT * DI];
__device__ __nv_bfloat16 g_Hd [NT * NR];
__device__ float g_P1[4 * NT * 256];
__device__ float g_P3[8 * NT * NR];

// ===================== single-block permutation =============================
__global__ void k_perm(const int* __restrict__ idx) {
    __shared__ int cnt[NE], off[NE], cur[NE];
    int tid = threadIdx.x;
    if (tid < NE) { cnt[tid] = 0; cur[tid] = 0; }
    __syncthreads();
    for (int t = tid; t < NT; t += 1024) atomicAdd(&cnt[idx[t]], 1);
    __syncthreads();
    if (tid == 0) {
        int s = 0;
        for (int e = 0; e < NE; ++e) { off[e] = s; g_offsets[e] = s; s += cnt[e]; }
        g_offsets[NE] = s;
    }
    __syncthreads();
    for (int t = tid; t < NT; t += 1024) {
        int e = idx[t];
        int p = atomicAdd(&cur[e], 1);
        g_perm[off[e] + p] = t;
    }
}

// ===================== one-shot conversion kernel ===========================
__device__ __forceinline__ uint2 cvt4(float4 v) {
    __nv_bfloat162 lo = __floats2bfloat162_rn(v.x, v.y);
    __nv_bfloat162 hi = __floats2bfloat162_rn(v.z, v.w);
    uint2 o; o.x = *(uint32_t*)&lo; o.y = *(uint32_t*)&hi;
    return o;
}

#define R0N (NT * DH / 4)
#define RA1 (NE * 128 * DH / 4)
#define RA3 (NE * NR * DI / 4)
#define RCT (NR * NR)

__global__ void conv_all(
    const float* __restrict__ x,
    const float* __restrict__ gate_A, const float* __restrict__ up_A,
    const float* __restrict__ down_A,
    const float* __restrict__ gate_C, const float* __restrict__ up_C,
    const float* __restrict__ down_C,
    __nv_bfloat16* __restrict__ Xb, __nv_bfloat16* __restrict__ W1,
    __nv_bfloat16* __restrict__ Ad,
    __nv_bfloat16* __restrict__ CgT, __nv_bfloat16* __restrict__ CuT,
    __nv_bfloat16* __restrict__ CdT)
{
    int r = blockIdx.y;
    int stride = gridDim.x * 256;
    int i0 = blockIdx.x * 256 + threadIdx.x;
    if (r == 0) {
        for (int i = i0; i < R0N; i += stride)
            ((uint2*)Xb)[i] = cvt4(((const float4*)x)[i]);
    } else if (r == 1) {
        for (int i = i0; i < RA1; i += stride) {
            int e = i / (128 * DH / 4), off = i % (128 * DH / 4);
            *(uint2*)(W1 + (size_t)e * 256 * DH + (size_t)off * 4) =
                cvt4(((const float4*)gate_A)[i]);
        }
    } else if (r == 2) {
        for (int i = i0; i < RA1; i += stride) {
            int e = i / (128 * DH / 4), off = i % (128 * DH / 4);
            *(uint2*)(W1 + (size_t)e * 256 * DH + (size_t)128 * DH + (size_t)off * 4) =
                cvt4(((const float4*)up_A)[i]);
        }
    } else if (r == 3) {
        for (int i = i0; i < RA3; i += stride)
            ((uint2*)Ad)[i] = cvt4(((const float4*)down_A)[i]);
    } else if (r == 4) {
        for (int i = i0; i < RCT; i += stride) {
            int s = i >> 7, rr = i & 127;
            CgT[rr * NR + s] = __float2bfloat16(gate_C[s * NR + rr]);
            CuT[rr * NR + s] = __float2bfloat16(up_C[s * NR + rr]);
        }
    } else {
        for (int i = i0; i < RCT; i += stride) {
            int s = i >> 7, rr = i & 127;
            CdT[rr * NR + s] = __float2bfloat16(down_C[s * NR + rr]);
        }
    }
}

// ===================== fused convert+fold kernel ============================
__global__ void __launch_bounds__(256) fold_b(
    const float* __restrict__ gate_B, const float* __restrict__ up_B,
    const float* __restrict__ down_B,
    const __nv_bfloat16* __restrict__ CgT, const __nv_bfloat16* __restrict__ CuT,
    const __nv_bfloat16* __restrict__ CdT,
    __nv_bfloat16* __restrict__ Bg, __nv_bfloat16* __restrict__ Bu,
    __nv_bfloat16* __restrict__ Bd)
{
    extern __shared__ char dsm[];
    uint32_t sb = smem_u32(dsm);
    uint32_t sA = sb, sC = sb + 4 * ABUF;
    char* pA = dsm;
    char* pC = dsm + 4 * ABUF;

    int z = blockIdx.x;
    int e = z / 104, w = z % 104;
    const float* src;
    const __nv_bfloat16* CT;
    __nv_bfloat16* dst;
    int row0;
    if (w < 44)      { src = gate_B + (size_t)e * DI * NR; CT = CgT; dst = g_Bg + (size_t)e * DI * NR; row0 = w * 128; }
    else if (w < 88) { src = up_B   + (size_t)e * DI * NR; CT = CuT; dst = g_Bu + (size_t)e * DI * NR; row0 = (w - 44) * 128; }
    else             { src = down_B + (size_t)e * DH * NR; CT = CdT; dst = g_Bd + (size_t)e * DH * NR; row0 = (w - 88) * 128; }
    (void)Bg; (void)Bu; (void)Bd;

    int tid = threadIdx.x;

    #pragma unroll
    for (int l = 0; l < 16; ++l) {
        int idx = tid + l * 256;
        int n = idx >> 5;
        int c4 = idx & 31;
        int col = c4 * 4;
        float4 v = *(const float4*)&src[(size_t)(row0 + n) * NR + col];
        int buf = col >> 5;
        int boff = (col & 31) * 2;
        *(uint2*)(pA + buf * ABUF + n * PITCH + boff) = cvt4(v);
    }
    #pragma unroll
    for (int l = 0; l < 8; ++l) {
        int idx = tid + l * 256;
        int r = idx >> 4;
        int ch = idx & 15;
        int scol = ch * 8;
        uint4 v = *(const uint4*)&CT[r * NR + scol];
        int buf = scol >> 5;
        int boff = (scol & 31) * 2;
        *(uint4*)(pC + buf * ABUF + r * PITCH + boff) = v;
    }
    __syncthreads();

    int lane = tid & 31, wid = tid >> 5;
    int wm = wid >> 1, wn = wid & 1;
    int gq = lane >> 2, tig = lane & 3;
    int l7 = lane & 7, lb3 = (lane >> 3) & 1, lb4 = (lane >> 4) & 1;

    uint32_t aLane = sA + (uint32_t)(wm * 32 + l7 + lb3 * 8) * PITCH + lb4 * 16;
    uint32_t bLane = sC + (uint32_t)(wn * 64 + l7 + lb4 * 8) * PITCH + lb3 * 16;

    float acc[2][8][4];
    #pragma unroll
    for (int mt = 0; mt < 2; ++mt)
        #pragma unroll
        for (int nt = 0; nt < 8; ++nt)
            #pragma unroll
            for (int j = 0; j < 4; ++j) acc[mt][nt][j] = 0.f;

    #pragma unroll
    for (int buf = 0; buf < 4; ++buf) {
        #pragma unroll
        for (int ks = 0; ks < 2; ++ks) {
            uint32_t a[2][4], b[8][2];
            uint32_t ab = aLane + buf * ABUF + ks * 32;
            #pragma unroll
            for (int mt = 0; mt < 2; ++mt)
                ldsm4(a[mt], ab + mt * 16 * PITCH);
            uint32_t bb = bLane + buf * ABUF + ks * 32;
            #pragma unroll
            for (int p = 0; p < 4; ++p) {
                uint32_t q[4];
                ldsm4(q, bb + p * 16 * PITCH);
                b[2 * p][0] = q[0]; b[2 * p][1] = q[1];
                b[2 * p + 1][0] = q[2]; b[2 * p + 1][1] = q[3];
            }
            #pragma unroll
            for (int mt = 0; mt < 2; ++mt)
                #pragma unroll
                for (int nt = 0; nt < 8; ++nt)
                    mma_bf16(acc[mt][nt], a[mt], b[nt]);
        }
    }

    #pragma unroll
    for (int mt = 0; mt < 2; ++mt) {
        #pragma unroll
        for (int half = 0; half < 2; ++half) {
            int r = wm * 32 + mt * 16 + half * 8 + gq;
            size_t rowoff = (size_t)(row0 + r) * NR;
            #pragma unroll
            for (int nt = 0; nt < 8; ++nt) {
                int cc = wn * 64 + nt * 8 + 2 * tig;
                __nv_bfloat162 o = __floats2bfloat162_rn(
                    acc[mt][nt][half * 2 + 0], acc[mt][nt][half * 2 + 1]);
                *(uint32_t*)&dst[rowoff + cc] = *(uint32_t*)&o;
            }
        }
    }
}

// ===================== bf16 MMA GEMM (R10-proven 2-stage) ===================
// D[i][n] = sum_k A[i][k] * B[n][k].  BM=128, BN=128, BK=32, cp.async dbl-buf.
// EPI 0: fp32 store (+split offset). EPI 2: fp32 +bias +perm scatter. EPI 3: bf16.
template<bool GATHER, bool WEIGHTS, int EPI, int SPLITK>
__global__ void __launch_bounds__(256, 2) mma1(
    const __nv_bfloat16* __restrict__ A, int lda, size_t strideAe, int Mtot,
    const __nv_bfloat16* __restrict__ B, int ldb, size_t strideBe, int Ktot,
    void* __restrict__ outp, int ldc, size_t splitStride,
    const float* __restrict__ bias)
{
    extern __shared__ char dsm[];
    uint32_t sb = smem_u32(dsm);
    uint32_t sA = sb, sB = sb + 2 * ABUF;
    int* rows = (int*)(dsm + 4 * ABUF);

    int z = blockIdx.z;
    int e, base, iend;
    if (WEIGHTS) { e = z; base = 0; iend = Mtot; }
    else {
        e = z / SPLITK;
        base = g_offsets[e]; iend = g_offsets[e + 1];
    }
    int sk = WEIGHTS ? 0 : (z % SPLITK);
    int i0 = base + blockIdx.y * 128;
    if (i0 >= iend) return;
    int nb = blockIdx.x * 128;
    int tid = threadIdx.x;

    if (tid < 128) {
        int i = i0 + tid; if (i >= iend) i = iend - 1;
        rows[tid] = GATHER ? g_perm[i] : i;
    }
    __syncthreads();

    const __nv_bfloat16* Ap = A + (WEIGHTS ? (size_t)e * strideAe : 0);
    const __nv_bfloat16* Bp = B + (size_t)e * strideBe;

    int kstep = Ktot / SPLITK;
    int kbeg  = sk * kstep;
    int nk    = kstep / 32;

    int lane = tid & 31, wid = tid >> 5;
    int wm = wid >> 1, wn = wid & 1;
    int gq = lane >> 2, tig = lane & 3;
    int l7 = lane & 7, lb3 = (lane >> 3) & 1, lb4 = (lane >> 4) & 1;

    uint32_t aLane = sA + (uint32_t)(wm * 32 + l7 + lb3 * 8) * PITCH + lb4 * 16;
    uint32_t bLane = sB + (uint32_t)(wn * 64 + l7 + lb4 * 8) * PITCH + lb3 * 16;

    float acc[2][8][4];
    #pragma unroll
    for (int mt = 0; mt < 2; ++mt)
        #pragma unroll
        for (int nt = 0; nt < 8; ++nt)
            #pragma unroll
            for (int j = 0; j < 4; ++j) acc[mt][nt][j] = 0.f;

    // prologue
    {
        #pragma unroll
        for (int l = 0; l < 2; ++l) {
            int idx = tid + l * 256;
            int r = idx >> 2, ch = idx & 3;
            CP16(sA + r * PITCH + ch * 16,
                 Ap + (size_t)rows[r] * lda + kbeg + ch * 8);
        }
        #pragma unroll
        for (int l = 0; l < 2; ++l) {
            int idx = tid + l * 256;
            int n = idx >> 2, ch = idx & 3;
            CP16(sB + n * PITCH + ch * 16,
                 Bp + (size_t)(nb + n) * ldb + kbeg + ch * 8);
        }
        CPCOMMIT();
    }

    for (int t = 0; t < nk; ++t) {
        int buf = t & 1;
        if (t + 1 < nk) {
            int kb = kbeg + (t + 1) * 32;
            int nbuf = buf ^ 1;
            #pragma unroll
            for (int l = 0; l < 2; ++l) {
                int idx = tid + l * 256;
                int r = idx >> 2, ch = idx & 3;
                CP16(sA + nbuf * ABUF + r * PITCH + ch * 16,
                     Ap + (size_t)rows[r] * lda + kb + ch * 8);
            }
            #pragma unroll
            for (int l = 0; l < 2; ++l) {
                int idx = tid + l * 256;
                int n = idx >> 2, ch = idx & 3;
                CP16(sB + nbuf * BBUF + n * PITCH + ch * 16,
                     Bp + (size_t)(nb + n) * ldb + kb + ch * 8);
            }
            CPCOMMIT();
            CPWAIT(1);
        } else {
            CPWAIT(0);
        }
        __syncthreads();

        #pragma unroll
        for (int ks = 0; ks < 2; ++ks) {
            uint32_t a[2][4], b[8][2];
            uint32_t ab = aLane + buf * ABUF + ks * 32;
            #pragma unroll
            for (int mt = 0; mt < 2; ++mt)
                ldsm4(a[mt], ab + mt * 16 * PITCH);
            uint32_t bb = bLane + buf * BBUF + ks * 32;
            #pragma unroll
            for (int p = 0; p < 4; ++p) {
                uint32_t q[4];
                ldsm4(q, bb + p * 16 * PITCH);
                b[2 * p][0] = q[0]; b[2 * p][1] = q[1];
                b[2 * p + 1][0] = q[2]; b[2 * p + 1][1] = q[3];
            }
            #pragma unroll
            for (int mt = 0; mt < 2; ++mt)
                #pragma unroll
                for (int nt = 0; nt < 8; ++nt)
                    mma_bf16(acc[mt][nt], a[mt], b[nt]);
        }
        __syncthreads();
    }

    // epilogue
    float* Cf = (float*)outp;
    __nv_bfloat16* Cb = (__nv_bfloat16*)outp;
    if (EPI == 0) Cf += (size_t)sk * splitStride;
    if (EPI == 3 && WEIGHTS) Cb += (size_t)e * (size_t)Mtot * ldc;

    #pragma unroll
    for (int mt = 0; mt < 2; ++mt) {
        #pragma unroll
        for (int half = 0; half < 2; ++half) {
            int r = wm * 32 + mt * 16 + half * 8 + gq;
            int gi = i0 + r;
            if (gi >= iend) continue;
            int orow = (EPI == 2) ? g_perm[gi] : gi;
            size_t rowoff = (size_t)orow * ldc + nb;
            #pragma unroll
            for (int nt = 0; nt < 8; ++nt) {
                int cc = wn * 64 + nt * 8 + 2 * tig;
                float v0 = acc[mt][nt][half * 2 + 0];
                float v1 = acc[mt][nt][half * 2 + 1];
                if (EPI == 0) {
                    *(float2*)&Cf[rowoff + cc] = make_float2(v0, v1);
                } else if (EPI == 2) {
                    const float* bp = bias + (size_t)e * DH + nb + cc;
                    *(float2*)&Cf[rowoff + cc] = make_float2(v0 + bp[0], v1 + bp[1]);
                } else {
                    __nv_bfloat162 o = __floats2bfloat162_rn(v0, v1);
                    *(uint32_t*)&Cb[rowoff + cc] = *(uint32_t*)&o;
                }
            }
        }
    }
}

// ===================== fused gate/up GEMM + SwiGLU (R10 2-stage) ============
__global__ void __launch_bounds__(256, 2) mma2(
    const __nv_bfloat16* __restrict__ H2,
    const __nv_bfloat16* __restrict__ Bgw, const __nv_bfloat16* __restrict__ Buw,
    __nv_bfloat16* __restrict__ Y)
{
    extern __shared__ char dsm[];
    uint32_t sb = smem_u32(dsm);
    uint32_t sAg = sb, sAu = sb + 2 * ABUF;
    uint32_t sBg = sb + 4 * ABUF, sBu = sb + 4 * ABUF + 2 * BBUF2;

    int e = blockIdx.z;
    int base = g_offsets[e], iend = g_offsets[e + 1];
    int i0 = base + blockIdx.y * 128;
    if (i0 >= iend) return;
    int nb = blockIdx.x * 64;
    int tid = threadIdx.x;

    const __nv_bfloat16* Bg = Bgw + (size_t)e * DI * NR;
    const __nv_bfloat16* Bu = Buw + (size_t)e * DI * NR;

    int lane = tid & 31, wid = tid >> 5;
    int wm = wid >> 1, wn = wid & 1;
    int gq = lane >> 2, tig = lane & 3;
    int l7 = lane & 7, lb3 = (lane >> 3) & 1, lb4 = (lane >> 4) & 1;

    uint32_t aOffL = (uint32_t)(wm * 32 + l7 + lb3 * 8) * PITCH + lb4 * 16;
    uint32_t bOffL = (uint32_t)(wn * 32 + l7 + lb4 * 8) * PITCH + lb3 * 16;

    float accG[2][4][4], accU[2][4][4];
    #pragma unroll
    for (int mt = 0; mt < 2; ++mt)
        #pragma unroll
        for (int nt = 0; nt < 4; ++nt)
            #pragma unroll
            for (int j = 0; j < 4; ++j) { accG[mt][nt][j] = 0.f; accU[mt][nt][j] = 0.f; }

    const int nk = 4;
    auto rowOf = [&](int r) { int i = i0 + r; return (i < iend) ? i : (iend - 1); };

    {
        #pragma unroll
        for (int l = 0; l < 4; ++l) {
            int idx = tid + l * 256;
            int st = idx >> 9, rr = (idx >> 2) & 127, ch = idx & 3;
            uint32_t dst = (st ? sAu : sAg) + rr * PITCH + ch * 16;
            CP16(dst, H2 + (size_t)rowOf(rr) * 256 + st * 128 + 0 + ch * 8);
        }
        #pragma unroll
        for (int l = 0; l < 2; ++l) {
            int idx = tid + l * 256;
            int st = idx >> 8, n = (idx >> 2) & 63, ch = idx & 3;
            const __nv_bfloat16* src = (st ? Bu : Bg) + (size_t)(nb + n) * NR + 0 + ch * 8;
            uint32_t dst = (st ? sBu : sBg) + n * PITCH + ch * 16;
            CP16(dst, src);
        }
        CPCOMMIT();
    }

    for (int t = 0; t < nk; ++t) {
        int buf = t & 1;
        if (t + 1 < nk) {
            int kb = (t + 1) * 32;
            int nbuf = buf ^ 1;
            #pragma unroll
            for (int l = 0; l < 4; ++l) {
                int idx = tid + l * 256;
                int st = idx >> 9, rr = (idx >> 2) & 127, ch = idx & 3;
                uint32_t dst = (st ? sAu : sAg) + nbuf * ABUF + rr * PITCH + ch * 16;
                CP16(dst, H2 + (size_t)rowOf(rr) * 256 + st * 128 + kb + ch * 8);
            }
            #pragma unroll
            for (int l = 0; l < 2; ++l) {
                int idx = tid + l * 256;
                int st = idx >> 8, n = (idx >> 2) & 63, ch = idx & 3;
                const __nv_bfloat16* src = (st ? Bu : Bg) + (size_t)(nb + n) * NR + kb + ch * 8;
                uint32_t dst = (st ? sBu : sBg) + nbuf * BBUF2 + n * PITCH + ch * 16;
                CP16(dst, src);
            }
            CPCOMMIT();
            CPWAIT(1);
        } else {
            CPWAIT(0);
        }
        __syncthreads();

        #pragma unroll
        for (int ks = 0; ks < 2; ++ks) {
            uint32_t ag[2][4], au[2][4], bg[4][2], bu[4][2];
            uint32_t abg = sAg + buf * ABUF + aOffL + ks * 32;
            uint32_t abu = sAu + buf * ABUF + aOffL + ks * 32;
            #pragma unroll
            for (int mt = 0; mt < 2; ++mt) {
                ldsm4(ag[mt], abg + mt * 16 * PITCH);
                ldsm4(au[mt], abu + mt * 16 * PITCH);
            }
            uint32_t bbg = sBg + buf * BBUF2 + bOffL + ks * 32;
            uint32_t bbu = sBu + buf * BBUF2 + bOffL + ks * 32;
            #pragma unroll
            for (int p = 0; p < 2; ++p) {
                uint32_t qg[4], qu[4];
                ldsm4(qg, bbg + p * 16 * PITCH);
                ldsm4(qu, bbu + p * 16 * PITCH);
                bg[2 * p][0] = qg[0]; bg[2 * p][1] = qg[1];
                bg[2 * p + 1][0] = qg[2]; bg[2 * p + 1][1] = qg[3];
                bu[2 * p][0] = qu[0]; bu[2 * p][1] = qu[1];
                bu[2 * p + 1][0] = qu[2]; bu[2 * p + 1][1] = qu[3];
            }
            #pragma unroll
            for (int mt = 0; mt < 2; ++mt)
                #pragma unroll
                for (int nt = 0; nt < 4; ++nt) {
                    mma_bf16(accG[mt][nt], ag[mt], bg[nt]);
                    mma_bf16(accU[mt][nt], au[mt], bu[nt]);
                }
        }
        __syncthreads();
    }

    #pragma unroll
    for (int mt = 0; mt < 2; ++mt) {
        #pragma unroll
        for (int half = 0; half < 2; ++half) {
            int r = wm * 32 + mt * 16 + half * 8 + gq;
            int gi = i0 + r;
            if (gi >= iend) continue;
            size_t rowoff = (size_t)gi * DI + nb;
            #pragma unroll
            for (int nt = 0; nt < 4; ++nt) {
                int cc = wn * 32 + nt * 8 + 2 * tig;
                float g0 = accG[mt][nt][half * 2 + 0];
                float g1 = accG[mt][nt][half * 2 + 1];
                float u0 = accU[mt][nt][half * 2 + 0];
                float u1 = accU[mt][nt][half * 2 + 1];
                float y0 = u0 * g0 / (1.f + __expf(-g0));
                float y1 = u1 * g1 / (1.f + __expf(-g1));
                __nv_bfloat162 o = __floats2bfloat162_rn(y0, y1);
                *(uint32_t*)&Y[rowoff + cc] = *(uint32_t*)&o;
            }
        }
    }
}

// ===================== split-K reduce -> bf16 ================================
template<int SR>
__global__ void reduce_bf(const float4* __restrict__ P, uint2* __restrict__ O,
                          int n4, size_t stride4)
{
    int i = blockIdx.x * 256 + threadIdx.x;
    if (i >= n4) return;
    float4 s = P[i];
    #pragma unroll
    for (int k = 1; k < SR; ++k) {
        float4 v = P[(size_t)k * stride4 + i];
        s.x += v.x; s.y += v.y; s.z += v.z; s.w += v.w;
    }
    __nv_bfloat162 lo = __floats2bfloat162_rn(s.x, s.y);
    __nv_bfloat162 hi = __floats2bfloat162_rn(s.z, s.w);
    uint2 o; o.x = *(uint32_t*)&lo; o.y = *(uint32_t*)&hi;
    O[i] = o;
}

// ===================== launch ================================================
extern "C" void kernel_launch(void* const* d_in, const int* in_sizes, int n_in,
                              void* d_out, int out_size)
{
    const float* x         = (const float*)d_in[0];
    const int*   eidx      = (const int*)  d_in[1];
    const float* gate_A    = (const float*)d_in[2];
    const float* gate_C    = (const float*)d_in[3];
    const float* gate_B    = (const float*)d_in[4];
    const float* up_A      = (const float*)d_in[5];
    const float* up_C      = (const float*)d_in[6];
    const float* up_B      = (const float*)d_in[7];
    const float* down_A    = (const float*)d_in[8];
    const float* down_C    = (const float*)d_in[9];
    const float* down_B    = (const float*)d_in[10];
    const float* down_bias = (const float*)d_in[11];
    float* out = (float*)d_out;

    __nv_bfloat16 *pXb, *pW1, *pAd, *pBg, *pBu, *pBd, *pCgT, *pCuT, *pCdT,
                  *pH, *pY, *pHd;
    float *pP1, *pP3;
    cudaGetSymbolAddress((void**)&pXb,  g_Xb);
    cudaGetSymbolAddress((void**)&pW1,  g_W1);
    cudaGetSymbolAddress((void**)&pAd,  g_Ad);
    cudaGetSymbolAddress((void**)&pBg,  g_Bg);
    cudaGetSymbolAddress((void**)&pBu,  g_Bu);
    cudaGetSymbolAddress((void**)&pBd,  g_Bd);
    cudaGetSymbolAddress((void**)&pCgT, g_CgT);
    cudaGetSymbolAddress((void**)&pCuT, g_CuT);
    cudaGetSymbolAddress((void**)&pCdT, g_CdT);
    cudaGetSymbolAddress((void**)&pH,   g_H);
    cudaGetSymbolAddress((void**)&pY,   g_Y);
    cudaGetSymbolAddress((void**)&pHd,  g_Hd);
    cudaGetSymbolAddress((void**)&pP1,  g_P1);
    cudaGetSymbolAddress((void**)&pP3,  g_P3);

    const int SM1 = 4 * ABUF + 1024;               // 41984 (2 CTAs/SM)
    const int SM2 = 4 * ABUF + 4 * BBUF2 + 512;    // 61952
    const int SMF = 8 * ABUF;                      // 81920
    cudaFuncSetAttribute(mma1<true,  false, 0, 2>, cudaFuncAttributeMaxDynamicSharedMemorySize, SM1);
    cudaFuncSetAttribute(mma1<false, false, 0, 8>, cudaFuncAttributeMaxDynamicSharedMemorySize, SM1);
    cudaFuncSetAttribute(mma1<false, false, 2, 1>, cudaFuncAttributeMaxDynamicSharedMemorySize, SM1);
    cudaFuncSetAttribute(mma2, cudaFuncAttributeMaxDynamicSharedMemorySize, SM2);
    cudaFuncSetAttribute(fold_b, cudaFuncAttributeMaxDynamicSharedMemorySize, SMF);

    // permutation (1) + conversions/transposes (1) + fused folds (1)
    k_perm<<<1, 1024>>>(eidx);
    conv_all<<<dim3(1024, 6), 256>>>(
        x, gate_A, up_A, down_A, gate_C, up_C, down_C,
        pXb, pW1, pAd, pCgT, pCuT, pCdT);
    fold_b<<<NE * 104, 256, SMF>>>(
        gate_B, up_B, down_B, pCgT, pCuT, pCdT, pBg, pBu, pBd);

    // K1: H = x_perm @ [gate_A; up_A]^T   (split-K 2, fp32 partials)
    mma1<true, false, 0, 2><<<dim3(2, NT / 128, NE * 2), 256, SM1>>>(
        pXb, DH, 0, 0, pW1, DH, (size_t)256 * DH, DH,
        pP1, 256, (size_t)NT * 256, nullptr);
    reduce_bf<2><<<(NT * 256 / 4 + 255) / 256, 256>>>(
        (const float4*)pP1, (uint2*)pH, NT * 256 / 4, (size_t)NT * 256 / 4);

    // K2: Y = silu(Hg @ Bg'^T) * (Hu @ Bu'^T)
    mma2<<<dim3(DI / 64, NT / 128, NE), 256, SM2>>>(pH, pBg, pBu, pY);

    // K3: Hd = Y @ down_A^T   (split-K 8)
    mma1<false, false, 0, 8><<<dim3(1, NT / 128, NE * 8), 256, SM1>>>(
        pY, DI, 0, 0, pAd, DI, (size_t)NR * DI, DI,
        pP3, NR, (size_t)NT * NR, nullptr);
    reduce_bf<8><<<(NT * NR / 4 + 255) / 256, 256>>>(
        (const float4*)pP3, (uint2*)pHd, NT * NR / 4, (size_t)NT * NR / 4);

    // K4: out[perm[i],:] = Hd @ Bd'^T + bias[e]
    mma1<false, false, 2, 1><<<dim3(DH / 128, NT / 128, NE), 256, SM1>>>(
        pHd, NR, 0, 0, pBd, NR, (size_t)DH * NR, NR,
        out, DH, 0, down_bias);
}

// round 13
// speedup vs baseline: 1.1279x; 1.1033x over previous
#include <cuda_runtime.h>
#include <cuda_bf16.h>
#include <cstdint>

#define NE 8
#define NT 4096
#define DH 2048
#define DI 5632
#define NR 128
#define PITCH 80          // bytes per 32-bf16 smem row (conflict-free for LDSM)
#define ABUF 10240        // 128 rows * 80B
#define BBUF 10240
#define BBUF2 5120        // 64 rows * 80B
#define TMAX 40           // max token tiles: sum ceil(cnt_e/128) <= 32+7

// ===================== low-level helpers ====================================
__device__ __forceinline__ uint32_t smem_u32(const void* p) {
    uint32_t a;
    asm("{ .reg .u64 t; cvta.to.shared.u64 t, %1; cvt.u32.u64 %0, t; }"
        : "=r"(a) : "l"(p));
    return a;
}
#define CP16(dst, src) \
    asm volatile("cp.async.cg.shared.global [%0], [%1], 16;" \
                 :: "r"(dst), "l"(src) : "memory")
#define CPCOMMIT() asm volatile("cp.async.commit_group;" ::: "memory")
#define CPWAIT(n)  asm volatile("cp.async.wait_group %0;" :: "n"(n) : "memory")

__device__ __forceinline__ void ldsm4(uint32_t r[4], uint32_t addr) {
    asm volatile("ldmatrix.sync.aligned.m8n8.x4.shared.b16 {%0,%1,%2,%3}, [%4];"
        : "=r"(r[0]), "=r"(r[1]), "=r"(r[2]), "=r"(r[3]) : "r"(addr));
}

__device__ __forceinline__ void mma_bf16(
    float c[4], const uint32_t a[4], const uint32_t b[2])
{
    asm volatile(
        "mma.sync.aligned.m16n8k16.row.col.f32.bf16.bf16.f32 "
        "{%0,%1,%2,%3}, {%4,%5,%6,%7}, {%8,%9}, {%0,%1,%2,%3};"
        : "+f"(c[0]), "+f"(c[1]), "+f"(c[2]), "+f"(c[3])
        : "r"(a[0]), "r"(a[1]), "r"(a[2]), "r"(a[3]),
          "r"(b[0]), "r"(b[1]));
}

// ===================== scratch globals ======================================
__device__ int g_offsets[NE + 1];
__device__ int g_perm[NT];
__device__ int g_ntiles;
__device__ int g_tile_e [TMAX + 8];
__device__ int g_tile_i0[TMAX + 8];

__device__ __nv_bfloat16 g_Xb [NT * DH];
__device__ __nv_bfloat16 g_W1 [NE * 256 * DH];  // rows 0..127 gate_A, 128..255 up_A
__device__ __nv_bfloat16 g_Ad [NE * NR * DI];
__device__ __nv_bfloat16 g_Bg [NE * DI * NR];   // folded: gate_B @ gate_C
__device__ __nv_bfloat16 g_Bu [NE * DI * NR];   // folded: up_B @ up_C
__device__ __nv_bfloat16 g_Bd [NE * DH * NR];   // folded: down_B @ down_C
__device__ __nv_bfloat16 g_CgT[NR * NR];        // gate_C^T
__device__ __nv_bfloat16 g_CuT[NR * NR];
__device__ __nv_bfloat16 g_CdT[NR * NR];
__device__ __nv_bfloat16 g_H  [NT * 256];
__device__ __nv_bfloat16 g_Y  [NT * DI];
__device__ __nv_bfloat16 g_Hd [NT * NR];
__device__ float g_P1[4 * NT * 256];
__device__ float g_P3[8 * NT * NR];

// ===================== single-block permutation + tile table ================
__global__ void k_perm(const int* __restrict__ idx) {
    __shared__ int cnt[NE], off[NE], cur[NE];
    int tid = threadIdx.x;
    if (tid < NE) { cnt[tid] = 0; cur[tid] = 0; }
    __syncthreads();
    for (int t = tid; t < NT; t += 1024) atomicAdd(&cnt[idx[t]], 1);
    __syncthreads();
    if (tid == 0) {
        int s = 0;
        for (int e = 0; e < NE; ++e) { off[e] = s; g_offsets[e] = s; s += cnt[e]; }
        g_offsets[NE] = s;
        int nt2 = 0;
        for (int e = 0; e < NE; ++e)
            for (int i0 = off[e]; i0 < off[e] + cnt[e]; i0 += 128) {
                g_tile_e[nt2] = e; g_tile_i0[nt2] = i0; ++nt2;
            }
        g_ntiles = nt2;
    }
    __syncthreads();
    for (int t = tid; t < NT; t += 1024) {
        int e = idx[t];
        int p = atomicAdd(&cur[e], 1);
        g_perm[off[e] + p] = t;
    }
}

// ===================== one-shot conversion kernel ===========================
__device__ __forceinline__ uint2 cvt4(float4 v) {
    __nv_bfloat162 lo = __floats2bfloat162_rn(v.x, v.y);
    __nv_bfloat162 hi = __floats2bfloat162_rn(v.z, v.w);
    uint2 o; o.x = *(uint32_t*)&lo; o.y = *(uint32_t*)&hi;
    return o;
}

#define R0N (NT * DH / 4)
#define RA1 (NE * 128 * DH / 4)
#define RA3 (NE * NR * DI / 4)
#define RCT (NR * NR)

__global__ void conv_all(
    const float* __restrict__ x,
    const float* __restrict__ gate_A, const float* __restrict__ up_A,
    const float* __restrict__ down_A,
    const float* __restrict__ gate_C, const float* __restrict__ up_C,
    const float* __restrict__ down_C,
    __nv_bfloat16* __restrict__ Xb, __nv_bfloat16* __restrict__ W1,
    __nv_bfloat16* __restrict__ Ad,
    __nv_bfloat16* __restrict__ CgT, __nv_bfloat16* __restrict__ CuT,
    __nv_bfloat16* __restrict__ CdT)
{
    int r = blockIdx.y;
    int stride = gridDim.x * 256;
    int i0 = blockIdx.x * 256 + threadIdx.x;
    if (r == 0) {
        for (int i = i0; i < R0N; i += stride)
            ((uint2*)Xb)[i] = cvt4(((const float4*)x)[i]);
    } else if (r == 1) {
        for (int i = i0; i < RA1; i += stride) {
            int e = i / (128 * DH / 4), off = i % (128 * DH / 4);
            *(uint2*)(W1 + (size_t)e * 256 * DH + (size_t)off * 4) =
                cvt4(((const float4*)gate_A)[i]);
        }
    } else if (r == 2) {
        for (int i = i0; i < RA1; i += stride) {
            int e = i / (128 * DH / 4), off = i % (128 * DH / 4);
            *(uint2*)(W1 + (size_t)e * 256 * DH + (size_t)128 * DH + (size_t)off * 4) =
                cvt4(((const float4*)up_A)[i]);
        }
    } else if (r == 3) {
        for (int i = i0; i < RA3; i += stride)
            ((uint2*)Ad)[i] = cvt4(((const float4*)down_A)[i]);
    } else if (r == 4) {
        for (int i = i0; i < RCT; i += stride) {
            int s = i >> 7, rr = i & 127;
            CgT[rr * NR + s] = __float2bfloat16(gate_C[s * NR + rr]);
            CuT[rr * NR + s] = __float2bfloat16(up_C[s * NR + rr]);
        }
    } else {
        for (int i = i0; i < RCT; i += stride) {
            int s = i >> 7, rr = i & 127;
            CdT[rr * NR + s] = __float2bfloat16(down_C[s * NR + rr]);
        }
    }
}

// ===================== fused convert+fold kernel ============================
__global__ void __launch_bounds__(256) fold_b(
    const float* __restrict__ gate_B, const float* __restrict__ up_B,
    const float* __restrict__ down_B,
    const __nv_bfloat16* __restrict__ CgT, const __nv_bfloat16* __restrict__ CuT,
    const __nv_bfloat16* __restrict__ CdT)
{
    extern __shared__ char dsm[];
    uint32_t sb = smem_u32(dsm);
    uint32_t sA = sb, sC = sb + 4 * ABUF;
    char* pA = dsm;
    char* pC = dsm + 4 * ABUF;

    int z = blockIdx.x;
    int e = z / 104, w = z % 104;
    const float* src;
    const __nv_bfloat16* CT;
    __nv_bfloat16* dst;
    int row0;
    if (w < 44)      { src = gate_B + (size_t)e * DI * NR; CT = CgT; dst = g_Bg + (size_t)e * DI * NR; row0 = w * 128; }
    else if (w < 88) { src = up_B   + (size_t)e * DI * NR; CT = CuT; dst = g_Bu + (size_t)e * DI * NR; row0 = (w - 44) * 128; }
    else             { src = down_B + (size_t)e * DH * NR; CT = CdT; dst = g_Bd + (size_t)e * DH * NR; row0 = (w - 88) * 128; }

    int tid = threadIdx.x;

    #pragma unroll
    for (int l = 0; l < 16; ++l) {
        int idx = tid + l * 256;
        int n = idx >> 5;
        int c4 = idx & 31;
        int col = c4 * 4;
        float4 v = *(const float4*)&src[(size_t)(row0 + n) * NR + col];
        int buf = col >> 5;
        int boff = (col & 31) * 2;
        *(uint2*)(pA + buf * ABUF + n * PITCH + boff) = cvt4(v);
    }
    #pragma unroll
    for (int l = 0; l < 8; ++l) {
        int idx = tid + l * 256;
        int r = idx >> 4;
        int ch = idx & 15;
        int scol = ch * 8;
        uint4 v = *(const uint4*)&CT[r * NR + scol];
        int buf = scol >> 5;
        int boff = (scol & 31) * 2;
        *(uint4*)(pC + buf * ABUF + r * PITCH + boff) = v;
    }
    __syncthreads();

    int lane = tid & 31, wid = tid >> 5;
    int wm = wid >> 1, wn = wid & 1;
    int gq = lane >> 2, tig = lane & 3;
    int l7 = lane & 7, lb3 = (lane >> 3) & 1, lb4 = (lane >> 4) & 1;

    uint32_t aLane = sA + (uint32_t)(wm * 32 + l7 + lb3 * 8) * PITCH + lb4 * 16;
    uint32_t bLane = sC + (uint32_t)(wn * 64 + l7 + lb4 * 8) * PITCH + lb3 * 16;

    float acc[2][8][4];
    #pragma unroll
    for (int mt = 0; mt < 2; ++mt)
        #pragma unroll
        for (int nt = 0; nt < 8; ++nt)
            #pragma unroll
            for (int j = 0; j < 4; ++j) acc[mt][nt][j] = 0.f;

    #pragma unroll
    for (int buf = 0; buf < 4; ++buf) {
        #pragma unroll
        for (int ks = 0; ks < 2; ++ks) {
            uint32_t a[2][4], b[8][2];
            uint32_t ab = aLane + buf * ABUF + ks * 32;
            #pragma unroll
            for (int mt = 0; mt < 2; ++mt)
                ldsm4(a[mt], ab + mt * 16 * PITCH);
            uint32_t bb = bLane + buf * ABUF + ks * 32;
            #pragma unroll
            for (int p = 0; p < 4; ++p) {
                uint32_t q[4];
                ldsm4(q, bb + p * 16 * PITCH);
                b[2 * p][0] = q[0]; b[2 * p][1] = q[1];
                b[2 * p + 1][0] = q[2]; b[2 * p + 1][1] = q[3];
            }
            #pragma unroll
            for (int mt = 0; mt < 2; ++mt)
                #pragma unroll
                for (int nt = 0; nt < 8; ++nt)
                    mma_bf16(acc[mt][nt], a[mt], b[nt]);
        }
    }

    #pragma unroll
    for (int mt = 0; mt < 2; ++mt) {
        #pragma unroll
        for (int half = 0; half < 2; ++half) {
            int r = wm * 32 + mt * 16 + half * 8 + gq;
            size_t rowoff = (size_t)(row0 + r) * NR;
            #pragma unroll
            for (int nt = 0; nt < 8; ++nt) {
                int cc = wn * 64 + nt * 8 + 2 * tig;
                __nv_bfloat162 o = __floats2bfloat162_rn(
                    acc[mt][nt][half * 2 + 0], acc[mt][nt][half * 2 + 1]);
                *(uint32_t*)&dst[rowoff + cc] = *(uint32_t*)&o;
            }
        }
    }
}

// ===================== bf16 MMA GEMM (R10 2-stage, tile-table grid) =========
// D[i][n] = sum_k A[i][k] * B[n][k].  BM=128, BN=128, BK=32, cp.async dbl-buf.
// grid: (n-tiles, TMAX, SPLITK).  EPI 0: fp32 store (+split). EPI 2: +bias+scatter.
template<bool GATHER, int EPI, int SPLITK>
__global__ void __launch_bounds__(256, 2) mma1(
    const __nv_bfloat16* __restrict__ A, int lda,
    const __nv_bfloat16* __restrict__ B, int ldb, size_t strideBe, int Ktot,
    void* __restrict__ outp, int ldc, size_t splitStride,
    const float* __restrict__ bias)
{
    extern __shared__ char dsm[];
    uint32_t sb = smem_u32(dsm);
    uint32_t sA = sb, sB = sb + 2 * ABUF;
    int* rows = (int*)(dsm + 4 * ABUF);

    int ty = blockIdx.y;
    if (ty >= g_ntiles) return;
    int e  = g_tile_e[ty];
    int i0 = g_tile_i0[ty];
    int iend = g_offsets[e + 1];
    int sk = blockIdx.z;
    int nb = blockIdx.x * 128;
    int tid = threadIdx.x;

    if (tid < 128) {
        int i = i0 + tid; if (i >= iend) i = iend - 1;
        rows[tid] = GATHER ? g_perm[i] : i;
    }
    __syncthreads();

    const __nv_bfloat16* Bp = B + (size_t)e * strideBe;

    int kstep = Ktot / SPLITK;
    int kbeg  = sk * kstep;
    int nk    = kstep / 32;

    int lane = tid & 31, wid = tid >> 5;
    int wm = wid >> 1, wn = wid & 1;
    int gq = lane >> 2, tig = lane & 3;
    int l7 = lane & 7, lb3 = (lane >> 3) & 1, lb4 = (lane >> 4) & 1;

    uint32_t aLane = sA + (uint32_t)(wm * 32 + l7 + lb3 * 8) * PITCH + lb4 * 16;
    uint32_t bLane = sB + (uint32_t)(wn * 64 + l7 + lb4 * 8) * PITCH + lb3 * 16;

    float acc[2][8][4];
    #pragma unroll
    for (int mt = 0; mt < 2; ++mt)
        #pragma unroll
        for (int nt = 0; nt < 8; ++nt)
            #pragma unroll
            for (int j = 0; j < 4; ++j) acc[mt][nt][j] = 0.f;

    // prologue
    {
        #pragma unroll
        for (int l = 0; l < 2; ++l) {
            int idx = tid + l * 256;
            int r = idx >> 2, ch = idx & 3;
            CP16(sA + r * PITCH + ch * 16,
                 A + (size_t)rows[r] * lda + kbeg + ch * 8);
        }
        #pragma unroll
        for (int l = 0; l < 2; ++l) {
            int idx = tid + l * 256;
            int n = idx >> 2, ch = idx & 3;
            CP16(sB + n * PITCH + ch * 16,
                 Bp + (size_t)(nb + n) * ldb + kbeg + ch * 8);
        }
        CPCOMMIT();
    }

    for (int t = 0; t < nk; ++t) {
        int buf = t & 1;
        if (t + 1 < nk) {
            int kb = kbeg + (t + 1) * 32;
            int nbuf = buf ^ 1;
            #pragma unroll
            for (int l = 0; l < 2; ++l) {
                int idx = tid + l * 256;
                int r = idx >> 2, ch = idx & 3;
                CP16(sA + nbuf * ABUF + r * PITCH + ch * 16,
                     A + (size_t)rows[r] * lda + kb + ch * 8);
            }
            #pragma unroll
            for (int l = 0; l < 2; ++l) {
                int idx = tid + l * 256;
                int n = idx >> 2, ch = idx & 3;
                CP16(sB + nbuf * BBUF + n * PITCH + ch * 16,
                     Bp + (size_t)(nb + n) * ldb + kb + ch * 8);
            }
            CPCOMMIT();
            CPWAIT(1);
        } else {
            CPWAIT(0);
        }
        __syncthreads();

        #pragma unroll
        for (int ks = 0; ks < 2; ++ks) {
            uint32_t a[2][4], b[8][2];
            uint32_t ab = aLane + buf * ABUF + ks * 32;
            #pragma unroll
            for (int mt = 0; mt < 2; ++mt)
                ldsm4(a[mt], ab + mt * 16 * PITCH);
            uint32_t bb = bLane + buf * BBUF + ks * 32;
            #pragma unroll
            for (int p = 0; p < 4; ++p) {
                uint32_t q[4];
                ldsm4(q, bb + p * 16 * PITCH);
                b[2 * p][0] = q[0]; b[2 * p][1] = q[1];
                b[2 * p + 1][0] = q[2]; b[2 * p + 1][1] = q[3];
            }
            #pragma unroll
            for (int mt = 0; mt < 2; ++mt)
                #pragma unroll
                for (int nt = 0; nt < 8; ++nt)
                    mma_bf16(acc[mt][nt], a[mt], b[nt]);
        }
        __syncthreads();
    }

    // epilogue
    float* Cf = (float*)outp;
    __nv_bfloat16* Cb = (__nv_bfloat16*)outp;
    if (EPI == 0) Cf += (size_t)sk * splitStride;

    #pragma unroll
    for (int mt = 0; mt < 2; ++mt) {
        #pragma unroll
        for (int half = 0; half < 2; ++half) {
            int r = wm * 32 + mt * 16 + half * 8 + gq;
            int gi = i0 + r;
            if (gi >= iend) continue;
            int orow = (EPI == 2) ? g_perm[gi] : gi;
            size_t rowoff = (size_t)orow * ldc + nb;
            #pragma unroll
            for (int nt = 0; nt < 8; ++nt) {
                int cc = wn * 64 + nt * 8 + 2 * tig;
                float v0 = acc[mt][nt][half * 2 + 0];
                float v1 = acc[mt][nt][half * 2 + 1];
                if (EPI == 0) {
                    *(float2*)&Cf[rowoff + cc] = make_float2(v0, v1);
                } else if (EPI == 2) {
                    const float* bp = bias + (size_t)e * DH + nb + cc;
                    *(float2*)&Cf[rowoff + cc] = make_float2(v0 + bp[0], v1 + bp[1]);
                } else {
                    __nv_bfloat162 o = __floats2bfloat162_rn(v0, v1);
                    *(uint32_t*)&Cb[rowoff + cc] = *(uint32_t*)&o;
                }
            }
        }
    }
}

// ===================== fused gate/up GEMM + SwiGLU (tile-table grid) ========
__global__ void __launch_bounds__(256, 2) mma2(
    const __nv_bfloat16* __restrict__ H2,
    const __nv_bfloat16* __restrict__ Bgw, const __nv_bfloat16* __restrict__ Buw,
    __nv_bfloat16* __restrict__ Y)
{
    extern __shared__ char dsm[];
    uint32_t sb = smem_u32(dsm);
    uint32_t sAg = sb, sAu = sb + 2 * ABUF;
    uint32_t sBg = sb + 4 * ABUF, sBu = sb + 4 * ABUF + 2 * BBUF2;

    int ty = blockIdx.y;
    if (ty >= g_ntiles) return;
    int e  = g_tile_e[ty];
    int i0 = g_tile_i0[ty];
    int iend = g_offsets[e + 1];
    int nb = blockIdx.x * 64;
    int tid = threadIdx.x;

    const __nv_bfloat16* Bg = Bgw + (size_t)e * DI * NR;
    const __nv_bfloat16* Bu = Buw + (size_t)e * DI * NR;

    int lane = tid & 31, wid = tid >> 5;
    int wm = wid >> 1, wn = wid & 1;
    int gq = lane >> 2, tig = lane & 3;
    int l7 = lane & 7, lb3 = (lane >> 3) & 1, lb4 = (lane >> 4) & 1;

    uint32_t aOffL = (uint32_t)(wm * 32 + l7 + lb3 * 8) * PITCH + lb4 * 16;
    uint32_t bOffL = (uint32_t)(wn * 32 + l7 + lb4 * 8) * PITCH + lb3 * 16;

    float accG[2][4][4], accU[2][4][4];
    #pragma unroll
    for (int mt = 0; mt < 2; ++mt)
        #pragma unroll
        for (int nt = 0; nt < 4; ++nt)
            #pragma unroll
            for (int j = 0; j < 4; ++j) { accG[mt][nt][j] = 0.f; accU[mt][nt][j] = 0.f; }

    const int nk = 4;
    auto rowOf = [&](int r) { int i = i0 + r; return (i < iend) ? i : (iend - 1); };

    {
        #pragma unroll
        for (int l = 0; l < 4; ++l) {
            int idx = tid + l * 256;
            int st = idx >> 9, rr = (idx >> 2) & 127, ch = idx & 3;
            uint32_t dst = (st ? sAu : sAg) + rr * PITCH + ch * 16;
            CP16(dst, H2 + (size_t)rowOf(rr) * 256 + st * 128 + 0 + ch * 8);
        }
        #pragma unroll
        for (int l = 0; l < 2; ++l) {
            int idx = tid + l * 256;
            int st = idx >> 8, n = (idx >> 2) & 63, ch = idx & 3;
            const __nv_bfloat16* src = (st ? Bu : Bg) + (size_t)(nb + n) * NR + 0 + ch * 8;
            uint32_t dst = (st ? sBu : sBg) + n * PITCH + ch * 16;
            CP16(dst, src);
        }
        CPCOMMIT();
    }

    for (int t = 0; t < nk; ++t) {
        int buf = t & 1;
        if (t + 1 < nk) {
            int kb = (t + 1) * 32;
            int nbuf = buf ^ 1;
            #pragma unroll
            for (int l = 0; l < 4; ++l) {
                int idx = tid + l * 256;
                int st = idx >> 9, rr = (idx >> 2) & 127, ch = idx & 3;
                uint32_t dst = (st ? sAu : sAg) + nbuf * ABUF + rr * PITCH + ch * 16;
                CP16(dst, H2 + (size_t)rowOf(rr) * 256 + st * 128 + kb + ch * 8);
            }
            #pragma unroll
            for (int l = 0; l < 2; ++l) {
                int idx = tid + l * 256;
                int st = idx >> 8, n = (idx >> 2) & 63, ch = idx & 3;
                const __nv_bfloat16* src = (st ? Bu : Bg) + (size_t)(nb + n) * NR + kb + ch * 8;
                uint32_t dst = (st ? sBu : sBg) + nbuf * BBUF2 + n * PITCH + ch * 16;
                CP16(dst, src);
            }
            CPCOMMIT();
            CPWAIT(1);
        } else {
            CPWAIT(0);
        }
        __syncthreads();

        #pragma unroll
        for (int ks = 0; ks < 2; ++ks) {
            uint32_t ag[2][4], au[2][4], bg[4][2], bu[4][2];
            uint32_t abg = sAg + buf * ABUF + aOffL + ks * 32;
            uint32_t abu = sAu + buf * ABUF + aOffL + ks * 32;
            #pragma unroll
            for (int mt = 0; mt < 2; ++mt) {
                ldsm4(ag[mt], abg + mt * 16 * PITCH);
                ldsm4(au[mt], abu + mt * 16 * PITCH);
            }
            uint32_t bbg = sBg + buf * BBUF2 + bOffL + ks * 32;
            uint32_t bbu = sBu + buf * BBUF2 + bOffL + ks * 32;
            #pragma unroll
            for (int p = 0; p < 2; ++p) {
                uint32_t qg[4], qu[4];
                ldsm4(qg, bbg + p * 16 * PITCH);
                ldsm4(qu, bbu + p * 16 * PITCH);
                bg[2 * p][0] = qg[0]; bg[2 * p][1] = qg[1];
                bg[2 * p + 1][0] = qg[2]; bg[2 * p + 1][1] = qg[3];
                bu[2 * p][0] = qu[0]; bu[2 * p][1] = qu[1];
                bu[2 * p + 1][0] = qu[2]; bu[2 * p + 1][1] = qu[3];
            }
            #pragma unroll
            for (int mt = 0; mt < 2; ++mt)
                #pragma unroll
                for (int nt = 0; nt < 4; ++nt) {
                    mma_bf16(accG[mt][nt], ag[mt], bg[nt]);
                    mma_bf16(accU[mt][nt], au[mt], bu[nt]);
                }
        }
        __syncthreads();
    }

    #pragma unroll
    for (int mt = 0; mt < 2; ++mt) {
        #pragma unroll
        for (int half = 0; half < 2; ++half) {
            int r = wm * 32 + mt * 16 + half * 8 + gq;
            int gi = i0 + r;
            if (gi >= iend) continue;
            size_t rowoff = (size_t)gi * DI + nb;
            #pragma unroll
            for (int nt = 0; nt < 4; ++nt) {
                int cc = wn * 32 + nt * 8 + 2 * tig;
                float g0 = accG[mt][nt][half * 2 + 0];
                float g1 = accG[mt][nt][half * 2 + 1];
                float u0 = accU[mt][nt][half * 2 + 0];
                float u1 = accU[mt][nt][half * 2 + 1];
                float y0 = u0 * g0 / (1.f + __expf(-g0));
                float y1 = u1 * g1 / (1.f + __expf(-g1));
                __nv_bfloat162 o = __floats2bfloat162_rn(y0, y1);
                *(uint32_t*)&Y[rowoff + cc] = *(uint32_t*)&o;
            }
        }
    }
}

// ===================== split-K reduce -> bf16 ================================
template<int SR>
__global__ void reduce_bf(const float4* __restrict__ P, uint2* __restrict__ O,
                          int n4, size_t stride4)
{
    int i = blockIdx.x * 256 + threadIdx.x;
    if (i >= n4) return;
    float4 s = P[i];
    #pragma unroll
    for (int k = 1; k < SR; ++k) {
        float4 v = P[(size_t)k * stride4 + i];
        s.x += v.x; s.y += v.y; s.z += v.z; s.w += v.w;
    }
    __nv_bfloat162 lo = __floats2bfloat162_rn(s.x, s.y);
    __nv_bfloat162 hi = __floats2bfloat162_rn(s.z, s.w);
    uint2 o; o.x = *(uint32_t*)&lo; o.y = *(uint32_t*)&hi;
    O[i] = o;
}

// ===================== launch ================================================
extern "C" void kernel_launch(void* const* d_in, const int* in_sizes, int n_in,
                              void* d_out, int out_size)
{
    const float* x         = (const float*)d_in[0];
    const int*   eidx      = (const int*)  d_in[1];
    const float* gate_A    = (const float*)d_in[2];
    const float* gate_C    = (const float*)d_in[3];
    const float* gate_B    = (const float*)d_in[4];
    const float* up_A      = (const float*)d_in[5];
    const float* up_C      = (const float*)d_in[6];
    const float* up_B      = (const float*)d_in[7];
    const float* down_A    = (const float*)d_in[8];
    const float* down_C    = (const float*)d_in[9];
    const float* down_B    = (const float*)d_in[10];
    const float* down_bias = (const float*)d_in[11];
    float* out = (float*)d_out;

    __nv_bfloat16 *pXb, *pW1, *pAd, *pBg, *pBu, *pBd, *pCgT, *pCuT, *pCdT,
                  *pH, *pY, *pHd;
    float *pP1, *pP3;
    cudaGetSymbolAddress((void**)&pXb,  g_Xb);
    cudaGetSymbolAddress((void**)&pW1,  g_W1);
    cudaGetSymbolAddress((void**)&pAd,  g_Ad);
    cudaGetSymbolAddress((void**)&pBg,  g_Bg);
    cudaGetSymbolAddress((void**)&pBu,  g_Bu);
    cudaGetSymbolAddress((void**)&pBd,  g_Bd);
    cudaGetSymbolAddress((void**)&pCgT, g_CgT);
    cudaGetSymbolAddress((void**)&pCuT, g_CuT);
    cudaGetSymbolAddress((void**)&pCdT, g_CdT);
    cudaGetSymbolAddress((void**)&pH,   g_H);
    cudaGetSymbolAddress((void**)&pY,   g_Y);
    cudaGetSymbolAddress((void**)&pHd,  g_Hd);
    cudaGetSymbolAddress((void**)&pP1,  g_P1);
    cudaGetSymbolAddress((void**)&pP3,  g_P3);

    const int SM1 = 4 * ABUF + 1024;               // 41984 (2 CTAs/SM)
    const int SM2 = 4 * ABUF + 4 * BBUF2 + 512;    // 61952
    const int SMF = 8 * ABUF;                      // 81920
    cudaFuncSetAttribute(mma1<true,  0, 4>, cudaFuncAttributeMaxDynamicSharedMemorySize, SM1);
    cudaFuncSetAttribute(mma1<false, 0, 8>, cudaFuncAttributeMaxDynamicSharedMemorySize, SM1);
    cudaFuncSetAttribute(mma1<false, 2, 1>, cudaFuncAttributeMaxDynamicSharedMemorySize, SM1);
    cudaFuncSetAttribute(mma2, cudaFuncAttributeMaxDynamicSharedMemorySize, SM2);
    cudaFuncSetAttribute(fold_b, cudaFuncAttributeMaxDynamicSharedMemorySize, SMF);

    // permutation + tile table (1) + conversions/transposes (1) + folds (1)
    k_perm<<<1, 1024>>>(eidx);
    conv_all<<<dim3(1024, 6), 256>>>(
        x, gate_A, up_A, down_A, gate_C, up_C, down_C,
        pXb, pW1, pAd, pCgT, pCuT, pCdT);
    fold_b<<<NE * 104, 256, SMF>>>(
        gate_B, up_B, down_B, pCgT, pCuT, pCdT);

    // K1: H = x_perm @ [gate_A; up_A]^T   (split-K 4, fp32 partials)
    mma1<true, 0, 4><<<dim3(2, TMAX, 4), 256, SM1>>>(
        pXb, DH, pW1, DH, (size_t)256 * DH, DH,
        pP1, 256, (size_t)NT * 256, nullptr);
    reduce_bf<4><<<(NT * 256 / 4 + 255) / 256, 256>>>(
        (const float4*)pP1, (uint2*)pH, NT * 256 / 4, (size_t)NT * 256 / 4);

    // K2: Y = silu(Hg @ Bg'^T) * (Hu @ Bu'^T)
    mma2<<<dim3(DI / 64, TMAX), 256, SM2>>>(pH, pBg, pBu, pY);

    // K3: Hd = Y @ down_A^T   (split-K 8)
    mma1<false, 0, 8><<<dim3(1, TMAX, 8), 256, SM1>>>(
        pY, DI, pAd, DI, (size_t)NR * DI, DI,
        pP3, NR, (size_t)NT * NR, nullptr);
    reduce_bf<8><<<(NT * NR / 4 + 255) / 256, 256>>>(
        (const float4*)pP3, (uint2*)pHd, NT * NR / 4, (size_t)NT * NR / 4);

    // K4: out[perm[i],:] = Hd @ Bd'^T + bias[e]
    mma1<false, 2, 1><<<dim3(DH / 128, TMAX, 1), 256, SM1>>>(
        pHd, NR, pBd, NR, (size_t)DH * NR, NR,
        out, DH, 0, down_bias);
}

// round 14
// speedup vs baseline: 1.1666x; 1.0343x over previous
#include <cuda_runtime.h>
#include <cuda_bf16.h>
#include <cstdint>

#define NE 8
#define NT 4096
#define DH 2048
#define DI 5632
#define NR 128
#define PITCH 80          // bytes per 32-bf16 smem row (conflict-free for LDSM)
#define ABUF 10240        // 128 rows * 80B
#define BBUF 10240
#define BBUF2 5120        // 64 rows * 80B
#define TMAX 40           // max token tiles: sum ceil(cnt_e/128) <= 32+7

// ===================== low-level helpers ====================================
__device__ __forceinline__ uint32_t smem_u32(const void* p) {
    uint32_t a;
    asm("{ .reg .u64 t; cvta.to.shared.u64 t, %1; cvt.u32.u64 %0, t; }"
        : "=r"(a) : "l"(p));
    return a;
}
#define CP16(dst, src) \
    asm volatile("cp.async.cg.shared.global [%0], [%1], 16;" \
                 :: "r"(dst), "l"(src) : "memory")
#define CPCOMMIT() asm volatile("cp.async.commit_group;" ::: "memory")
#define CPWAIT(n)  asm volatile("cp.async.wait_group %0;" :: "n"(n) : "memory")

__device__ __forceinline__ void ldsm4(uint32_t r[4], uint32_t addr) {
    asm volatile("ldmatrix.sync.aligned.m8n8.x4.shared.b16 {%0,%1,%2,%3}, [%4];"
        : "=r"(r[0]), "=r"(r[1]), "=r"(r[2]), "=r"(r[3]) : "r"(addr));
}

__device__ __forceinline__ void mma_bf16(
    float c[4], const uint32_t a[4], const uint32_t b[2])
{
    asm volatile(
        "mma.sync.aligned.m16n8k16.row.col.f32.bf16.bf16.f32 "
        "{%0,%1,%2,%3}, {%4,%5,%6,%7}, {%8,%9}, {%0,%1,%2,%3};"
        : "+f"(c[0]), "+f"(c[1]), "+f"(c[2]), "+f"(c[3])
        : "r"(a[0]), "r"(a[1]), "r"(a[2]), "r"(a[3]),
          "r"(b[0]), "r"(b[1]));
}

// ===================== scratch globals ======================================
__device__ int g_offsets[NE + 1];
__device__ int g_perm[NT];
__device__ int g_ntiles;
__device__ int g_tile_e [TMAX + 8];
__device__ int g_tile_i0[TMAX + 8];

__device__ __nv_bfloat16 g_Xb [NT * DH];
__device__ __nv_bfloat16 g_W1 [NE * 256 * DH];  // rows 0..127 gate_A, 128..255 up_A
__device__ __nv_bfloat16 g_Ad [NE * NR * DI];
__device__ __nv_bfloat16 g_Bg [NE * DI * NR];   // folded: gate_B @ gate_C
__device__ __nv_bfloat16 g_Bu [NE * DI * NR];   // folded: up_B @ up_C
__device__ __nv_bfloat16 g_Bd [NE * DH * NR];   // folded: down_B @ down_C
__device__ __nv_bfloat16 g_CgT[NR * NR];        // gate_C^T
__device__ __nv_bfloat16 g_CuT[NR * NR];
__device__ __nv_bfloat16 g_CdT[NR * NR];
__device__ __nv_bfloat16 g_H  [NT * 256];
__device__ __nv_bfloat16 g_Y  [NT * DI];
__device__ __nv_bfloat16 g_Hd [NT * NR];
__device__ float g_P1[4 * NT * 256];
__device__ float g_P3[8 * NT * NR];

// ===================== single-block permutation + tile table ================
__global__ void k_perm(const int* __restrict__ idx) {
    __shared__ int cnt[NE], off[NE], cur[NE];
    int tid = threadIdx.x;
    if (tid < NE) { cnt[tid] = 0; cur[tid] = 0; }
    __syncthreads();
    for (int t = tid; t < NT; t += 1024) atomicAdd(&cnt[idx[t]], 1);
    __syncthreads();
    if (tid == 0) {
        int s = 0;
        for (int e = 0; e < NE; ++e) { off[e] = s; g_offsets[e] = s; s += cnt[e]; }
        g_offsets[NE] = s;
        int nt2 = 0;
        for (int e = 0; e < NE; ++e)
            for (int i0 = off[e]; i0 < off[e] + cnt[e]; i0 += 128) {
                g_tile_e[nt2] = e; g_tile_i0[nt2] = i0; ++nt2;
            }
        g_ntiles = nt2;
    }
    __syncthreads();
    for (int t = tid; t < NT; t += 1024) {
        int e = idx[t];
        int p = atomicAdd(&cur[e], 1);
        g_perm[off[e] + p] = t;
    }
}

// ===================== conversion kernels ====================================
__device__ __forceinline__ uint2 cvt4(float4 v) {
    __nv_bfloat162 lo = __floats2bfloat162_rn(v.x, v.y);
    __nv_bfloat162 hi = __floats2bfloat162_rn(v.z, v.w);
    uint2 o; o.x = *(uint32_t*)&lo; o.y = *(uint32_t*)&hi;
    return o;
}

#define R0N (NT * DH / 4)
#define RA1 (NE * 128 * DH / 4)
#define RA3 (NE * NR * DI / 4)
#define RCT (NR * NR)

// main-stream conversions: K1 inputs (Xb, W1)
__global__ void conv_main(
    const float* __restrict__ x,
    const float* __restrict__ gate_A, const float* __restrict__ up_A,
    __nv_bfloat16* __restrict__ Xb, __nv_bfloat16* __restrict__ W1)
{
    int r = blockIdx.y;
    int stride = gridDim.x * 256;
    int i0 = blockIdx.x * 256 + threadIdx.x;
    if (r == 0) {
        for (int i = i0; i < R0N; i += stride)
            ((uint2*)Xb)[i] = cvt4(((const float4*)x)[i]);
    } else if (r == 1) {
        for (int i = i0; i < RA1; i += stride) {
            int e = i / (128 * DH / 4), off = i % (128 * DH / 4);
            *(uint2*)(W1 + (size_t)e * 256 * DH + (size_t)off * 4) =
                cvt4(((const float4*)gate_A)[i]);
        }
    } else {
        for (int i = i0; i < RA1; i += stride) {
            int e = i / (128 * DH / 4), off = i % (128 * DH / 4);
            *(uint2*)(W1 + (size_t)e * 256 * DH + (size_t)128 * DH + (size_t)off * 4) =
                cvt4(((const float4*)up_A)[i]);
        }
    }
}

// side-stream conversions: Ad + C transposes (feed fold_b / K3)
__global__ void conv_aux(
    const float* __restrict__ down_A,
    const float* __restrict__ gate_C, const float* __restrict__ up_C,
    const float* __restrict__ down_C,
    __nv_bfloat16* __restrict__ Ad,
    __nv_bfloat16* __restrict__ CgT, __nv_bfloat16* __restrict__ CuT,
    __nv_bfloat16* __restrict__ CdT)
{
    int r = blockIdx.y;
    int stride = gridDim.x * 256;
    int i0 = blockIdx.x * 256 + threadIdx.x;
    if (r == 0) {
        for (int i = i0; i < RA3; i += stride)
            ((uint2*)Ad)[i] = cvt4(((const float4*)down_A)[i]);
    } else if (r == 1) {
        for (int i = i0; i < RCT; i += stride) {
            int s = i >> 7, rr = i & 127;
            CgT[rr * NR + s] = __float2bfloat16(gate_C[s * NR + rr]);
            CuT[rr * NR + s] = __float2bfloat16(up_C[s * NR + rr]);
        }
    } else {
        for (int i = i0; i < RCT; i += stride) {
            int s = i >> 7, rr = i & 127;
            CdT[rr * NR + s] = __float2bfloat16(down_C[s * NR + rr]);
        }
    }
}

// ===================== fused convert+fold kernel ============================
__global__ void __launch_bounds__(256) fold_b(
    const float* __restrict__ gate_B, const float* __restrict__ up_B,
    const float* __restrict__ down_B,
    const __nv_bfloat16* __restrict__ CgT, const __nv_bfloat16* __restrict__ CuT,
    const __nv_bfloat16* __restrict__ CdT)
{
    extern __shared__ char dsm[];
    uint32_t sb = smem_u32(dsm);
    uint32_t sA = sb, sC = sb + 4 * ABUF;
    char* pA = dsm;
    char* pC = dsm + 4 * ABUF;

    int z = blockIdx.x;
    int e = z / 104, w = z % 104;
    const float* src;
    const __nv_bfloat16* CT;
    __nv_bfloat16* dst;
    int row0;
    if (w < 44)      { src = gate_B + (size_t)e * DI * NR; CT = CgT; dst = g_Bg + (size_t)e * DI * NR; row0 = w * 128; }
    else if (w < 88) { src = up_B   + (size_t)e * DI * NR; CT = CuT; dst = g_Bu + (size_t)e * DI * NR; row0 = (w - 44) * 128; }
    else             { src = down_B + (size_t)e * DH * NR; CT = CdT; dst = g_Bd + (size_t)e * DH * NR; row0 = (w - 88) * 128; }

    int tid = threadIdx.x;

    #pragma unroll
    for (int l = 0; l < 16; ++l) {
        int idx = tid + l * 256;
        int n = idx >> 5;
        int c4 = idx & 31;
        int col = c4 * 4;
        float4 v = *(const float4*)&src[(size_t)(row0 + n) * NR + col];
        int buf = col >> 5;
        int boff = (col & 31) * 2;
        *(uint2*)(pA + buf * ABUF + n * PITCH + boff) = cvt4(v);
    }
    #pragma unroll
    for (int l = 0; l < 8; ++l) {
        int idx = tid + l * 256;
        int r = idx >> 4;
        int ch = idx & 15;
        int scol = ch * 8;
        uint4 v = *(const uint4*)&CT[r * NR + scol];
        int buf = scol >> 5;
        int boff = (scol & 31) * 2;
        *(uint4*)(pC + buf * ABUF + r * PITCH + boff) = v;
    }
    __syncthreads();

    int lane = tid & 31, wid = tid >> 5;
    int wm = wid >> 1, wn = wid & 1;
    int gq = lane >> 2, tig = lane & 3;
    int l7 = lane & 7, lb3 = (lane >> 3) & 1, lb4 = (lane >> 4) & 1;

    uint32_t aLane = sA + (uint32_t)(wm * 32 + l7 + lb3 * 8) * PITCH + lb4 * 16;
    uint32_t bLane = sC + (uint32_t)(wn * 64 + l7 + lb4 * 8) * PITCH + lb3 * 16;

    float acc[2][8][4];
    #pragma unroll
    for (int mt = 0; mt < 2; ++mt)
        #pragma unroll
        for (int nt = 0; nt < 8; ++nt)
            #pragma unroll
            for (int j = 0; j < 4; ++j) acc[mt][nt][j] = 0.f;

    #pragma unroll
    for (int buf = 0; buf < 4; ++buf) {
        #pragma unroll
        for (int ks = 0; ks < 2; ++ks) {
            uint32_t a[2][4], b[8][2];
            uint32_t ab = aLane + buf * ABUF + ks * 32;
            #pragma unroll
            for (int mt = 0; mt < 2; ++mt)
                ldsm4(a[mt], ab + mt * 16 * PITCH);
            uint32_t bb = bLane + buf * ABUF + ks * 32;
            #pragma unroll
            for (int p = 0; p < 4; ++p) {
                uint32_t q[4];
                ldsm4(q, bb + p * 16 * PITCH);
                b[2 * p][0] = q[0]; b[2 * p][1] = q[1];
                b[2 * p + 1][0] = q[2]; b[2 * p + 1][1] = q[3];
            }
            #pragma unroll
            for (int mt = 0; mt < 2; ++mt)
                #pragma unroll
                for (int nt = 0; nt < 8; ++nt)
                    mma_bf16(acc[mt][nt], a[mt], b[nt]);
        }
    }

    #pragma unroll
    for (int mt = 0; mt < 2; ++mt) {
        #pragma unroll
        for (int half = 0; half < 2; ++half) {
            int r = wm * 32 + mt * 16 + half * 8 + gq;
            size_t rowoff = (size_t)(row0 + r) * NR;
            #pragma unroll
            for (int nt = 0; nt < 8; ++nt) {
                int cc = wn * 64 + nt * 8 + 2 * tig;
                __nv_bfloat162 o = __floats2bfloat162_rn(
                    acc[mt][nt][half * 2 + 0], acc[mt][nt][half * 2 + 1]);
                *(uint32_t*)&dst[rowoff + cc] = *(uint32_t*)&o;
            }
        }
    }
}

// ===================== bf16 MMA GEMM (R10 2-stage, tile-table grid) =========
template<bool GATHER, int EPI, int SPLITK>
__global__ void __launch_bounds__(256, 2) mma1(
    const __nv_bfloat16* __restrict__ A, int lda,
    const __nv_bfloat16* __restrict__ B, int ldb, size_t strideBe, int Ktot,
    void* __restrict__ outp, int ldc, size_t splitStride,
    const float* __restrict__ bias)
{
    extern __shared__ char dsm[];
    uint32_t sb = smem_u32(dsm);
    uint32_t sA = sb, sB = sb + 2 * ABUF;
    int* rows = (int*)(dsm + 4 * ABUF);

    int ty = blockIdx.y;
    if (ty >= g_ntiles) return;
    int e  = g_tile_e[ty];
    int i0 = g_tile_i0[ty];
    int iend = g_offsets[e + 1];
    int sk = blockIdx.z;
    int nb = blockIdx.x * 128;
    int tid = threadIdx.x;

    if (tid < 128) {
        int i = i0 + tid; if (i >= iend) i = iend - 1;
        rows[tid] = GATHER ? g_perm[i] : i;
    }
    __syncthreads();

    const __nv_bfloat16* Bp = B + (size_t)e * strideBe;

    int kstep = Ktot / SPLITK;
    int kbeg  = sk * kstep;
    int nk    = kstep / 32;

    int lane = tid & 31, wid = tid >> 5;
    int wm = wid >> 1, wn = wid & 1;
    int gq = lane >> 2, tig = lane & 3;
    int l7 = lane & 7, lb3 = (lane >> 3) & 1, lb4 = (lane >> 4) & 1;

    uint32_t aLane = sA + (uint32_t)(wm * 32 + l7 + lb3 * 8) * PITCH + lb4 * 16;
    uint32_t bLane = sB + (uint32_t)(wn * 64 + l7 + lb4 * 8) * PITCH + lb3 * 16;

    float acc[2][8][4];
    #pragma unroll
    for (int mt = 0; mt < 2; ++mt)
        #pragma unroll
        for (int nt = 0; nt < 8; ++nt)
            #pragma unroll
            for (int j = 0; j < 4; ++j) acc[mt][nt][j] = 0.f;

    // prologue
    {
        #pragma unroll
        for (int l = 0; l < 2; ++l) {
            int idx = tid + l * 256;
            int r = idx >> 2, ch = idx & 3;
            CP16(sA + r * PITCH + ch * 16,
                 A + (size_t)rows[r] * lda + kbeg + ch * 8);
        }
        #pragma unroll
        for (int l = 0; l < 2; ++l) {
            int idx = tid + l * 256;
            int n = idx >> 2, ch = idx & 3;
            CP16(sB + n * PITCH + ch * 16,
                 Bp + (size_t)(nb + n) * ldb + kbeg + ch * 8);
        }
        CPCOMMIT();
    }

    for (int t = 0; t < nk; ++t) {
        int buf = t & 1;
        if (t + 1 < nk) {
            int kb = kbeg + (t + 1) * 32;
            int nbuf = buf ^ 1;
            #pragma unroll
            for (int l = 0; l < 2; ++l) {
                int idx = tid + l * 256;
                int r = idx >> 2, ch = idx & 3;
                CP16(sA + nbuf * ABUF + r * PITCH + ch * 16,
                     A + (size_t)rows[r] * lda + kb + ch * 8);
            }
            #pragma unroll
            for (int l = 0; l < 2; ++l) {
                int idx = tid + l * 256;
                int n = idx >> 2, ch = idx & 3;
                CP16(sB + nbuf * BBUF + n * PITCH + ch * 16,
                     Bp + (size_t)(nb + n) * ldb + kb + ch * 8);
            }
            CPCOMMIT();
            CPWAIT(1);
        } else {
            CPWAIT(0);
        }
        __syncthreads();

        #pragma unroll
        for (int ks = 0; ks < 2; ++ks) {
            uint32_t a[2][4], b[8][2];
            uint32_t ab = aLane + buf * ABUF + ks * 32;
            #pragma unroll
            for (int mt = 0; mt < 2; ++mt)
                ldsm4(a[mt], ab + mt * 16 * PITCH);
            uint32_t bb = bLane + buf * BBUF + ks * 32;
            #pragma unroll
            for (int p = 0; p < 4; ++p) {
                uint32_t q[4];
                ldsm4(q, bb + p * 16 * PITCH);
                b[2 * p][0] = q[0]; b[2 * p][1] = q[1];
                b[2 * p + 1][0] = q[2]; b[2 * p + 1][1] = q[3];
            }
            #pragma unroll
            for (int mt = 0; mt < 2; ++mt)
                #pragma unroll
                for (int nt = 0; nt < 8; ++nt)
                    mma_bf16(acc[mt][nt], a[mt], b[nt]);
        }
        __syncthreads();
    }

    // epilogue
    float* Cf = (float*)outp;
    __nv_bfloat16* Cb = (__nv_bfloat16*)outp;
    if (EPI == 0) Cf += (size_t)sk * splitStride;

    #pragma unroll
    for (int mt = 0; mt < 2; ++mt) {
        #pragma unroll
        for (int half = 0; half < 2; ++half) {
            int r = wm * 32 + mt * 16 + half * 8 + gq;
            int gi = i0 + r;
            if (gi >= iend) continue;
            int orow = (EPI == 2) ? g_perm[gi] : gi;
            size_t rowoff = (size_t)orow * ldc + nb;
            #pragma unroll
            for (int nt = 0; nt < 8; ++nt) {
                int cc = wn * 64 + nt * 8 + 2 * tig;
                float v0 = acc[mt][nt][half * 2 + 0];
                float v1 = acc[mt][nt][half * 2 + 1];
                if (EPI == 0) {
                    *(float2*)&Cf[rowoff + cc] = make_float2(v0, v1);
                } else if (EPI == 2) {
                    const float* bp = bias + (size_t)e * DH + nb + cc;
                    *(float2*)&Cf[rowoff + cc] = make_float2(v0 + bp[0], v1 + bp[1]);
                } else {
                    __nv_bfloat162 o = __floats2bfloat162_rn(v0, v1);
                    *(uint32_t*)&Cb[rowoff + cc] = *(uint32_t*)&o;
                }
            }
        }
    }
}

// ===================== fused gate/up GEMM + SwiGLU (tile-table grid) ========
__global__ void __launch_bounds__(256, 2) mma2(
    const __nv_bfloat16* __restrict__ H2,
    const __nv_bfloat16* __restrict__ Bgw, const __nv_bfloat16* __restrict__ Buw,
    __nv_bfloat16* __restrict__ Y)
{
    extern __shared__ char dsm[];
    uint32_t sb = smem_u32(dsm);
    uint32_t sAg = sb, sAu = sb + 2 * ABUF;
    uint32_t sBg = sb + 4 * ABUF, sBu = sb + 4 * ABUF + 2 * BBUF2;

    int ty = blockIdx.y;
    if (ty >= g_ntiles) return;
    int e  = g_tile_e[ty];
    int i0 = g_tile_i0[ty];
    int iend = g_offsets[e + 1];
    int nb = blockIdx.x * 64;
    int tid = threadIdx.x;

    const __nv_bfloat16* Bg = Bgw + (size_t)e * DI * NR;
    const __nv_bfloat16* Bu = Buw + (size_t)e * DI * NR;

    int lane = tid & 31, wid = tid >> 5;
    int wm = wid >> 1, wn = wid & 1;
    int gq = lane >> 2, tig = lane & 3;
    int l7 = lane & 7, lb3 = (lane >> 3) & 1, lb4 = (lane >> 4) & 1;

    uint32_t aOffL = (uint32_t)(wm * 32 + l7 + lb3 * 8) * PITCH + lb4 * 16;
    uint32_t bOffL = (uint32_t)(wn * 32 + l7 + lb4 * 8) * PITCH + lb3 * 16;

    float accG[2][4][4], accU[2][4][4];
    #pragma unroll
    for (int mt = 0; mt < 2; ++mt)
        #pragma unroll
        for (int nt = 0; nt < 4; ++nt)
            #pragma unroll
            for (int j = 0; j < 4; ++j) { accG[mt][nt][j] = 0.f; accU[mt][nt][j] = 0.f; }

    const int nk = 4;
    auto rowOf = [&](int r) { int i = i0 + r; return (i < iend) ? i : (iend - 1); };

    {
        #pragma unroll
        for (int l = 0; l < 4; ++l) {
            int idx = tid + l * 256;
            int st = idx >> 9, rr = (idx >> 2) & 127, ch = idx & 3;
            uint32_t dst = (st ? sAu : sAg) + rr * PITCH + ch * 16;
            CP16(dst, H2 + (size_t)rowOf(rr) * 256 + st * 128 + 0 + ch * 8);
        }
        #pragma unroll
        for (int l = 0; l < 2; ++l) {
            int idx = tid + l * 256;
            int st = idx >> 8, n = (idx >> 2) & 63, ch = idx & 3;
            const __nv_bfloat16* src = (st ? Bu : Bg) + (size_t)(nb + n) * NR + 0 + ch * 8;
            uint32_t dst = (st ? sBu : sBg) + n * PITCH + ch * 16;
            CP16(dst, src);
        }
        CPCOMMIT();
    }

    for (int t = 0; t < nk; ++t) {
        int buf = t & 1;
        if (t + 1 < nk) {
            int kb = (t + 1) * 32;
            int nbuf = buf ^ 1;
            #pragma unroll
            for (int l = 0; l < 4; ++l) {
                int idx = tid + l * 256;
                int st = idx >> 9, rr = (idx >> 2) & 127, ch = idx & 3;
                uint32_t dst = (st ? sAu : sAg) + nbuf * ABUF + rr * PITCH + ch * 16;
                CP16(dst, H2 + (size_t)rowOf(rr) * 256 + st * 128 + kb + ch * 8);
            }
            #pragma unroll
            for (int l = 0; l < 2; ++l) {
                int idx = tid + l * 256;
                int st = idx >> 8, n = (idx >> 2) & 63, ch = idx & 3;
                const __nv_bfloat16* src = (st ? Bu : Bg) + (size_t)(nb + n) * NR + kb + ch * 8;
                uint32_t dst = (st ? sBu : sBg) + nbuf * BBUF2 + n * PITCH + ch * 16;
                CP16(dst, src);
            }
            CPCOMMIT();
            CPWAIT(1);
        } else {
            CPWAIT(0);
        }
        __syncthreads();

        #pragma unroll
        for (int ks = 0; ks < 2; ++ks) {
            uint32_t ag[2][4], au[2][4], bg[4][2], bu[4][2];
            uint32_t abg = sAg + buf * ABUF + aOffL + ks * 32;
            uint32_t abu = sAu + buf * ABUF + aOffL + ks * 32;
            #pragma unroll
            for (int mt = 0; mt < 2; ++mt) {
                ldsm4(ag[mt], abg + mt * 16 * PITCH);
                ldsm4(au[mt], abu + mt * 16 * PITCH);
            }
            uint32_t bbg = sBg + buf * BBUF2 + bOffL + ks * 32;
            uint32_t bbu = sBu + buf * BBUF2 + bOffL + ks * 32;
            #pragma unroll
            for (int p = 0; p < 2; ++p) {
                uint32_t qg[4], qu[4];
                ldsm4(qg, bbg + p * 16 * PITCH);
                ldsm4(qu, bbu + p * 16 * PITCH);
                bg[2 * p][0] = qg[0]; bg[2 * p][1] = qg[1];
                bg[2 * p + 1][0] = qg[2]; bg[2 * p + 1][1] = qg[3];
                bu[2 * p][0] = qu[0]; bu[2 * p][1] = qu[1];
                bu[2 * p + 1][0] = qu[2]; bu[2 * p + 1][1] = qu[3];
            }
            #pragma unroll
            for (int mt = 0; mt < 2; ++mt)
                #pragma unroll
                for (int nt = 0; nt < 4; ++nt) {
                    mma_bf16(accG[mt][nt], ag[mt], bg[nt]);
                    mma_bf16(accU[mt][nt], au[mt], bu[nt]);
                }
        }
        __syncthreads();
    }

    #pragma unroll
    for (int mt = 0; mt < 2; ++mt) {
        #pragma unroll
        for (int half = 0; half < 2; ++half) {
            int r = wm * 32 + mt * 16 + half * 8 + gq;
            int gi = i0 + r;
            if (gi >= iend) continue;
            size_t rowoff = (size_t)gi * DI + nb;
            #pragma unroll
            for (int nt = 0; nt < 4; ++nt) {
                int cc = wn * 32 + nt * 8 + 2 * tig;
                float g0 = accG[mt][nt][half * 2 + 0];
                float g1 = accG[mt][nt][half * 2 + 1];
                float u0 = accU[mt][nt][half * 2 + 0];
                float u1 = accU[mt][nt][half * 2 + 1];
                float y0 = u0 * g0 / (1.f + __expf(-g0));
                float y1 = u1 * g1 / (1.f + __expf(-g1));
                __nv_bfloat162 o = __floats2bfloat162_rn(y0, y1);
                *(uint32_t*)&Y[rowoff + cc] = *(uint32_t*)&o;
            }
        }
    }
}

// ===================== split-K reduce -> bf16 ================================
template<int SR>
__global__ void reduce_bf(const float4* __restrict__ P, uint2* __restrict__ O,
                          int n4, size_t stride4)
{
    int i = blockIdx.x * 256 + threadIdx.x;
    if (i >= n4) return;
    float4 s = P[i];
    #pragma unroll
    for (int k = 1; k < SR; ++k) {
        float4 v = P[(size_t)k * stride4 + i];
        s.x += v.x; s.y += v.y; s.z += v.z; s.w += v.w;
    }
    __nv_bfloat162 lo = __floats2bfloat162_rn(s.x, s.y);
    __nv_bfloat162 hi = __floats2bfloat162_rn(s.z, s.w);
    uint2 o; o.x = *(uint32_t*)&lo; o.y = *(uint32_t*)&hi;
    O[i] = o;
}

// ===================== launch ================================================
extern "C" void kernel_launch(void* const* d_in, const int* in_sizes, int n_in,
                              void* d_out, int out_size)
{
    const float* x         = (const float*)d_in[0];
    const int*   eidx      = (const int*)  d_in[1];
    const float* gate_A    = (const float*)d_in[2];
    const float* gate_C    = (const float*)d_in[3];
    const float* gate_B    = (const float*)d_in[4];
    const float* up_A      = (const float*)d_in[5];
    const float* up_C      = (const float*)d_in[6];
    const float* up_B      = (const float*)d_in[7];
    const float* down_A    = (const float*)d_in[8];
    const float* down_C    = (const float*)d_in[9];
    const float* down_B    = (const float*)d_in[10];
    const float* down_bias = (const float*)d_in[11];
    float* out = (float*)d_out;

    __nv_bfloat16 *pXb, *pW1, *pAd, *pBg, *pBu, *pBd, *pCgT, *pCuT, *pCdT,
                  *pH, *pY, *pHd;
    float *pP1, *pP3;
    cudaGetSymbolAddress((void**)&pXb,  g_Xb);
    cudaGetSymbolAddress((void**)&pW1,  g_W1);
    cudaGetSymbolAddress((void**)&pAd,  g_Ad);
    cudaGetSymbolAddress((void**)&pBg,  g_Bg);
    cudaGetSymbolAddress((void**)&pBu,  g_Bu);
    cudaGetSymbolAddress((void**)&pBd,  g_Bd);
    cudaGetSymbolAddress((void**)&pCgT, g_CgT);
    cudaGetSymbolAddress((void**)&pCuT, g_CuT);
    cudaGetSymbolAddress((void**)&pCdT, g_CdT);
    cudaGetSymbolAddress((void**)&pH,   g_H);
    cudaGetSymbolAddress((void**)&pY,   g_Y);
    cudaGetSymbolAddress((void**)&pHd,  g_Hd);
    cudaGetSymbolAddress((void**)&pP1,  g_P1);
    cudaGetSymbolAddress((void**)&pP3,  g_P3);

    const int SM1 = 4 * ABUF + 1024;               // 41984 (2 CTAs/SM)
    const int SM2 = 4 * ABUF + 4 * BBUF2 + 512;    // 61952
    const int SMF = 8 * ABUF;                      // 81920
    cudaFuncSetAttribute(mma1<true,  0, 4>, cudaFuncAttributeMaxDynamicSharedMemorySize, SM1);
    cudaFuncSetAttribute(mma1<false, 0, 8>, cudaFuncAttributeMaxDynamicSharedMemorySize, SM1);
    cudaFuncSetAttribute(mma1<false, 2, 1>, cudaFuncAttributeMaxDynamicSharedMemorySize, SM1);
    cudaFuncSetAttribute(mma2, cudaFuncAttributeMaxDynamicSharedMemorySize, SM2);
    cudaFuncSetAttribute(fold_b, cudaFuncAttributeMaxDynamicSharedMemorySize, SMF);

    // one-time handles (no device memory involved)
    static bool s_init = false;
    static cudaStream_t s1;
    static cudaEvent_t evFork, evPerm, evFold;
    if (!s_init) {
        cudaStreamCreateWithFlags(&s1, cudaStreamNonBlocking);
        cudaEventCreateWithFlags(&evFork, cudaEventDisableTiming);
        cudaEventCreateWithFlags(&evPerm, cudaEventDisableTiming);
        cudaEventCreateWithFlags(&evFold, cudaEventDisableTiming);
        s_init = true;
    }

    // fork side stream off the capture stream
    cudaEventRecord(evFork, 0);
    cudaStreamWaitEvent(s1, evFork, 0);

    // side stream: perm + aux conversions + weight folds
    k_perm<<<1, 1024, 0, s1>>>(eidx);
    cudaEventRecord(evPerm, s1);
    conv_aux<<<dim3(512, 3), 256, 0, s1>>>(
        down_A, gate_C, up_C, down_C, pAd, pCgT, pCuT, pCdT);
    fold_b<<<NE * 104, 256, SMF, s1>>>(
        gate_B, up_B, down_B, pCgT, pCuT, pCdT);
    cudaEventRecord(evFold, s1);

    // main stream: K1 inputs, then K1
    conv_main<<<dim3(1024, 3), 256>>>(x, gate_A, up_A, pXb, pW1);
    cudaStreamWaitEvent(0, evPerm, 0);

    // K1: H = x_perm @ [gate_A; up_A]^T   (split-K 4, fp32 partials)
    mma1<true, 0, 4><<<dim3(2, TMAX, 4), 256, SM1>>>(
        pXb, DH, pW1, DH, (size_t)256 * DH, DH,
        pP1, 256, (size_t)NT * 256, nullptr);
    reduce_bf<4><<<(NT * 256 / 4 + 255) / 256, 256>>>(
        (const float4*)pP1, (uint2*)pH, NT * 256 / 4, (size_t)NT * 256 / 4);

    // join side stream before K2 (needs Bg/Bu; K3 needs Ad; K4 needs Bd)
    cudaStreamWaitEvent(0, evFold, 0);

    // K2: Y = silu(Hg @ Bg'^T) * (Hu @ Bu'^T)
    mma2<<<dim3(DI / 64, TMAX), 256, SM2>>>(pH, pBg, pBu, pY);

    // K3: Hd = Y @ down_A^T   (split-K 8)
    mma1<false, 0, 8><<<dim3(1, TMAX, 8), 256, SM1>>>(
        pY, DI, pAd, DI, (size_t)NR * DI, DI,
        pP3, NR, (size_t)NT * NR, nullptr);
    reduce_bf<8><<<(NT * NR / 4 + 255) / 256, 256>>>(
        (const float4*)pP3, (uint2*)pHd, NT * NR / 4, (size_t)NT * NR / 4);

    // K4: out[perm[i],:] = Hd @ Bd'^T + bias[e]
    mma1<false, 2, 1><<<dim3(DH / 128, TMAX, 1), 256, SM1>>>(
        pHd, NR, pBd, NR, (size_t)DH * NR, NR,
        out, DH, 0, down_bias);
}

// round 15
// speedup vs baseline: 1.4927x; 1.2795x over previous
#include <cuda_runtime.h>
#include <cuda_bf16.h>
#include <cstdint>

#define NE 8
#define NT 4096
#define DH 2048
#define DI 5632
#define NR 128
#define PITCH 80          // bytes per 32-bf16 smem row (conflict-free for LDSM)
#define ABUF 10240        // 128 rows * 80B
#define BBUF 10240
#define TMAX 40           // max token tiles
#define NGRP 8            // K2 n-groups
#define NPB 11            // n-blocks (of 64) per K2 CTA: 88/8
#define ACH 10240         // A chunk [128][PITCH]
#define BCH 5120          // B chunk [64][PITCH]
#define ASTR (4 * ACH)    // per-stream A (K=128 resident)
#define BSTR (4 * BCH)    // per-stream B buffer

// ===================== low-level helpers ====================================
__device__ __forceinline__ uint32_t smem_u32(const void* p) {
    uint32_t a;
    asm("{ .reg .u64 t; cvta.to.shared.u64 t, %1; cvt.u32.u64 %0, t; }"
        : "=r"(a) : "l"(p));
    return a;
}
#define CP16(dst, src) \
    asm volatile("cp.async.cg.shared.global [%0], [%1], 16;" \
                 :: "r"(dst), "l"(src) : "memory")
#define CPCOMMIT() asm volatile("cp.async.commit_group;" ::: "memory")
#define CPWAIT(n)  asm volatile("cp.async.wait_group %0;" :: "n"(n) : "memory")

__device__ __forceinline__ void ldsm4(uint32_t r[4], uint32_t addr) {
    asm volatile("ldmatrix.sync.aligned.m8n8.x4.shared.b16 {%0,%1,%2,%3}, [%4];"
        : "=r"(r[0]), "=r"(r[1]), "=r"(r[2]), "=r"(r[3]) : "r"(addr));
}

__device__ __forceinline__ void mma_bf16(
    float c[4], const uint32_t a[4], const uint32_t b[2])
{
    asm volatile(
        "mma.sync.aligned.m16n8k16.row.col.f32.bf16.bf16.f32 "
        "{%0,%1,%2,%3}, {%4,%5,%6,%7}, {%8,%9}, {%0,%1,%2,%3};"
        : "+f"(c[0]), "+f"(c[1]), "+f"(c[2]), "+f"(c[3])
        : "r"(a[0]), "r"(a[1]), "r"(a[2]), "r"(a[3]),
          "r"(b[0]), "r"(b[1]));
}

// ===================== scratch globals ======================================
__device__ int g_offsets[NE + 1];
__device__ int g_perm[NT];
__device__ int g_ntiles;
__device__ int g_tile_e [TMAX + 8];
__device__ int g_tile_i0[TMAX + 8];

__device__ __nv_bfloat16 g_Xb [NT * DH];
__device__ __nv_bfloat16 g_W1 [NE * 256 * DH];
__device__ __nv_bfloat16 g_Ad [NE * NR * DI];
__device__ __nv_bfloat16 g_Bg [NE * DI * NR];
__device__ __nv_bfloat16 g_Bu [NE * DI * NR];
__device__ __nv_bfloat16 g_Bd [NE * DH * NR];
__device__ __nv_bfloat16 g_CgT[NR * NR];
__device__ __nv_bfloat16 g_CuT[NR * NR];
__device__ __nv_bfloat16 g_CdT[NR * NR];
__device__ __nv_bfloat16 g_H  [NT * 256];
__device__ __nv_bfloat16 g_Y  [NT * DI];
__device__ __nv_bfloat16 g_Hd [NT * NR];
__device__ float g_P1[4 * NT * 256];
__device__ float g_P3[8 * NT * NR];

// ===================== single-block permutation + tile table ================
__global__ void k_perm(const int* __restrict__ idx) {
    __shared__ int cnt[NE], off[NE], cur[NE];
    int tid = threadIdx.x;
    if (tid < NE) { cnt[tid] = 0; cur[tid] = 0; }
    __syncthreads();
    for (int t = tid; t < NT; t += 1024) atomicAdd(&cnt[idx[t]], 1);
    __syncthreads();
    if (tid == 0) {
        int s = 0;
        for (int e = 0; e < NE; ++e) { off[e] = s; g_offsets[e] = s; s += cnt[e]; }
        g_offsets[NE] = s;
        int nt2 = 0;
        for (int e = 0; e < NE; ++e)
            for (int i0 = off[e]; i0 < off[e] + cnt[e]; i0 += 128) {
                g_tile_e[nt2] = e; g_tile_i0[nt2] = i0; ++nt2;
            }
        g_ntiles = nt2;
    }
    __syncthreads();
    for (int t = tid; t < NT; t += 1024) {
        int e = idx[t];
        int p = atomicAdd(&cur[e], 1);
        g_perm[off[e] + p] = t;
    }
}

// ===================== conversion kernels ====================================
__device__ __forceinline__ uint2 cvt4(float4 v) {
    __nv_bfloat162 lo = __floats2bfloat162_rn(v.x, v.y);
    __nv_bfloat162 hi = __floats2bfloat162_rn(v.z, v.w);
    uint2 o; o.x = *(uint32_t*)&lo; o.y = *(uint32_t*)&hi;
    return o;
}

#define R0N (NT * DH / 4)
#define RA1 (NE * 128 * DH / 4)
#define RA3 (NE * NR * DI / 4)
#define RCT (NR * NR)

__global__ void conv_main(
    const float* __restrict__ x,
    const float* __restrict__ gate_A, const float* __restrict__ up_A,
    __nv_bfloat16* __restrict__ Xb, __nv_bfloat16* __restrict__ W1)
{
    int r = blockIdx.y;
    int stride = gridDim.x * 256;
    int i0 = blockIdx.x * 256 + threadIdx.x;
    if (r == 0) {
        for (int i = i0; i < R0N; i += stride)
            ((uint2*)Xb)[i] = cvt4(((const float4*)x)[i]);
    } else if (r == 1) {
        for (int i = i0; i < RA1; i += stride) {
            int e = i / (128 * DH / 4), off = i % (128 * DH / 4);
            *(uint2*)(W1 + (size_t)e * 256 * DH + (size_t)off * 4) =
                cvt4(((const float4*)gate_A)[i]);
        }
    } else {
        for (int i = i0; i < RA1; i += stride) {
            int e = i / (128 * DH / 4), off = i % (128 * DH / 4);
            *(uint2*)(W1 + (size_t)e * 256 * DH + (size_t)128 * DH + (size_t)off * 4) =
                cvt4(((const float4*)up_A)[i]);
        }
    }
}

__global__ void conv_aux(
    const float* __restrict__ down_A,
    const float* __restrict__ gate_C, const float* __restrict__ up_C,
    const float* __restrict__ down_C,
    __nv_bfloat16* __restrict__ Ad,
    __nv_bfloat16* __restrict__ CgT, __nv_bfloat16* __restrict__ CuT,
    __nv_bfloat16* __restrict__ CdT)
{
    int r = blockIdx.y;
    int stride = gridDim.x * 256;
    int i0 = blockIdx.x * 256 + threadIdx.x;
    if (r == 0) {
        for (int i = i0; i < RA3; i += stride)
            ((uint2*)Ad)[i] = cvt4(((const float4*)down_A)[i]);
    } else if (r == 1) {
        for (int i = i0; i < RCT; i += stride) {
            int s = i >> 7, rr = i & 127;
            CgT[rr * NR + s] = __float2bfloat16(gate_C[s * NR + rr]);
            CuT[rr * NR + s] = __float2bfloat16(up_C[s * NR + rr]);
        }
    } else {
        for (int i = i0; i < RCT; i += stride) {
            int s = i >> 7, rr = i & 127;
            CdT[rr * NR + s] = __float2bfloat16(down_C[s * NR + rr]);
        }
    }
}

// ===================== fused convert+fold kernel ============================
__global__ void __launch_bounds__(256) fold_b(
    const float* __restrict__ gate_B, const float* __restrict__ up_B,
    const float* __restrict__ down_B,
    const __nv_bfloat16* __restrict__ CgT, const __nv_bfloat16* __restrict__ CuT,
    const __nv_bfloat16* __restrict__ CdT)
{
    extern __shared__ char dsm[];
    uint32_t sb = smem_u32(dsm);
    uint32_t sA = sb, sC = sb + 4 * ABUF;
    char* pA = dsm;
    char* pC = dsm + 4 * ABUF;

    int z = blockIdx.x;
    int e = z / 104, w = z % 104;
    const float* src;
    const __nv_bfloat16* CT;
    __nv_bfloat16* dst;
    int row0;
    if (w < 44)      { src = gate_B + (size_t)e * DI * NR; CT = CgT; dst = g_Bg + (size_t)e * DI * NR; row0 = w * 128; }
    else if (w < 88) { src = up_B   + (size_t)e * DI * NR; CT = CuT; dst = g_Bu + (size_t)e * DI * NR; row0 = (w - 44) * 128; }
    else             { src = down_B + (size_t)e * DH * NR; CT = CdT; dst = g_Bd + (size_t)e * DH * NR; row0 = (w - 88) * 128; }

    int tid = threadIdx.x;

    #pragma unroll
    for (int l = 0; l < 16; ++l) {
        int idx = tid + l * 256;
        int n = idx >> 5;
        int c4 = idx & 31;
        int col = c4 * 4;
        float4 v = *(const float4*)&src[(size_t)(row0 + n) * NR + col];
        int buf = col >> 5;
        int boff = (col & 31) * 2;
        *(uint2*)(pA + buf * ABUF + n * PITCH + boff) = cvt4(v);
    }
    #pragma unroll
    for (int l = 0; l < 8; ++l) {
        int idx = tid + l * 256;
        int r = idx >> 4;
        int ch = idx & 15;
        int scol = ch * 8;
        uint4 v = *(const uint4*)&CT[r * NR + scol];
        int buf = scol >> 5;
        int boff = (scol & 31) * 2;
        *(uint4*)(pC + buf * ABUF + r * PITCH + boff) = v;
    }
    __syncthreads();

    int lane = tid & 31, wid = tid >> 5;
    int wm = wid >> 1, wn = wid & 1;
    int gq = lane >> 2, tig = lane & 3;
    int l7 = lane & 7, lb3 = (lane >> 3) & 1, lb4 = (lane >> 4) & 1;

    uint32_t aLane = sA + (uint32_t)(wm * 32 + l7 + lb3 * 8) * PITCH + lb4 * 16;
    uint32_t bLane = sC + (uint32_t)(wn * 64 + l7 + lb4 * 8) * PITCH + lb3 * 16;

    float acc[2][8][4];
    #pragma unroll
    for (int mt = 0; mt < 2; ++mt)
        #pragma unroll
        for (int nt = 0; nt < 8; ++nt)
            #pragma unroll
            for (int j = 0; j < 4; ++j) acc[mt][nt][j] = 0.f;

    #pragma unroll
    for (int buf = 0; buf < 4; ++buf) {
        #pragma unroll
        for (int ks = 0; ks < 2; ++ks) {
            uint32_t a[2][4], b[8][2];
            uint32_t ab = aLane + buf * ABUF + ks * 32;
            #pragma unroll
            for (int mt = 0; mt < 2; ++mt)
                ldsm4(a[mt], ab + mt * 16 * PITCH);
            uint32_t bb = bLane + buf * ABUF + ks * 32;
            #pragma unroll
            for (int p = 0; p < 4; ++p) {
                uint32_t q[4];
                ldsm4(q, bb + p * 16 * PITCH);
                b[2 * p][0] = q[0]; b[2 * p][1] = q[1];
                b[2 * p + 1][0] = q[2]; b[2 * p + 1][1] = q[3];
            }
            #pragma unroll
            for (int mt = 0; mt < 2; ++mt)
                #pragma unroll
                for (int nt = 0; nt < 8; ++nt)
                    mma_bf16(acc[mt][nt], a[mt], b[nt]);
        }
    }

    #pragma unroll
    for (int mt = 0; mt < 2; ++mt) {
        #pragma unroll
        for (int half = 0; half < 2; ++half) {
            int r = wm * 32 + mt * 16 + half * 8 + gq;
            size_t rowoff = (size_t)(row0 + r) * NR;
            #pragma unroll
            for (int nt = 0; nt < 8; ++nt) {
                int cc = wn * 64 + nt * 8 + 2 * tig;
                __nv_bfloat162 o = __floats2bfloat162_rn(
                    acc[mt][nt][half * 2 + 0], acc[mt][nt][half * 2 + 1]);
                *(uint32_t*)&dst[rowoff + cc] = *(uint32_t*)&o;
            }
        }
    }
}

// ===================== bf16 MMA GEMM (R10 2-stage, tile-table grid) =========
template<bool GATHER, int EPI, int SPLITK>
__global__ void __launch_bounds__(256, 2) mma1(
    const __nv_bfloat16* __restrict__ A, int lda,
    const __nv_bfloat16* __restrict__ B, int ldb, size_t strideBe, int Ktot,
    void* __restrict__ outp, int ldc, size_t splitStride,
    const float* __restrict__ bias)
{
    extern __shared__ char dsm[];
    uint32_t sb = smem_u32(dsm);
    uint32_t sA = sb, sB = sb + 2 * ABUF;
    int* rows = (int*)(dsm + 4 * ABUF);

    int ty = blockIdx.y;
    if (ty >= g_ntiles) return;
    int e  = g_tile_e[ty];
    int i0 = g_tile_i0[ty];
    int iend = g_offsets[e + 1];
    int sk = blockIdx.z;
    int nb = blockIdx.x * 128;
    int tid = threadIdx.x;

    if (tid < 128) {
        int i = i0 + tid; if (i >= iend) i = iend - 1;
        rows[tid] = GATHER ? g_perm[i] : i;
    }
    __syncthreads();

    const __nv_bfloat16* Bp = B + (size_t)e * strideBe;

    int kstep = Ktot / SPLITK;
    int kbeg  = sk * kstep;
    int nk    = kstep / 32;

    int lane = tid & 31, wid = tid >> 5;
    int wm = wid >> 1, wn = wid & 1;
    int gq = lane >> 2, tig = lane & 3;
    int l7 = lane & 7, lb3 = (lane >> 3) & 1, lb4 = (lane >> 4) & 1;

    uint32_t aLane = sA + (uint32_t)(wm * 32 + l7 + lb3 * 8) * PITCH + lb4 * 16;
    uint32_t bLane = sB + (uint32_t)(wn * 64 + l7 + lb4 * 8) * PITCH + lb3 * 16;

    float acc[2][8][4];
    #pragma unroll
    for (int mt = 0; mt < 2; ++mt)
        #pragma unroll
        for (int nt = 0; nt < 8; ++nt)
            #pragma unroll
            for (int j = 0; j < 4; ++j) acc[mt][nt][j] = 0.f;

    // prologue
    {
        #pragma unroll
        for (int l = 0; l < 2; ++l) {
            int idx = tid + l * 256;
            int r = idx >> 2, ch = idx & 3;
            CP16(sA + r * PITCH + ch * 16,
                 A + (size_t)rows[r] * lda + kbeg + ch * 8);
        }
        #pragma unroll
        for (int l = 0; l < 2; ++l) {
            int idx = tid + l * 256;
            int n = idx >> 2, ch = idx & 3;
            CP16(sB + n * PITCH + ch * 16,
                 Bp + (size_t)(nb + n) * ldb + kbeg + ch * 8);
        }
        CPCOMMIT();
    }

    for (int t = 0; t < nk; ++t) {
        int buf = t & 1;
        if (t + 1 < nk) {
            int kb = kbeg + (t + 1) * 32;
            int nbuf = buf ^ 1;
            #pragma unroll
            for (int l = 0; l < 2; ++l) {
                int idx = tid + l * 256;
                int r = idx >> 2, ch = idx & 3;
                CP16(sA + nbuf * ABUF + r * PITCH + ch * 16,
                     A + (size_t)rows[r] * lda + kb + ch * 8);
            }
            #pragma unroll
            for (int l = 0; l < 2; ++l) {
                int idx = tid + l * 256;
                int n = idx >> 2, ch = idx & 3;
                CP16(sB + nbuf * BBUF + n * PITCH + ch * 16,
                     Bp + (size_t)(nb + n) * ldb + kb + ch * 8);
            }
            CPCOMMIT();
            CPWAIT(1);
        } else {
            CPWAIT(0);
        }
        __syncthreads();

        #pragma unroll
        for (int ks = 0; ks < 2; ++ks) {
            uint32_t a[2][4], b[8][2];
            uint32_t ab = aLane + buf * ABUF + ks * 32;
            #pragma unroll
            for (int mt = 0; mt < 2; ++mt)
                ldsm4(a[mt], ab + mt * 16 * PITCH);
            uint32_t bb = bLane + buf * BBUF + ks * 32;
            #pragma unroll
            for (int p = 0; p < 4; ++p) {
                uint32_t q[4];
                ldsm4(q, bb + p * 16 * PITCH);
                b[2 * p][0] = q[0]; b[2 * p][1] = q[1];
                b[2 * p + 1][0] = q[2]; b[2 * p + 1][1] = q[3];
            }
            #pragma unroll
            for (int mt = 0; mt < 2; ++mt)
                #pragma unroll
                for (int nt = 0; nt < 8; ++nt)
                    mma_bf16(acc[mt][nt], a[mt], b[nt]);
        }
        __syncthreads();
    }

    // epilogue
    float* Cf = (float*)outp;
    __nv_bfloat16* Cb = (__nv_bfloat16*)outp;
    if (EPI == 0) Cf += (size_t)sk * splitStride;

    #pragma unroll
    for (int mt = 0; mt < 2; ++mt) {
        #pragma unroll
        for (int half = 0; half < 2; ++half) {
            int r = wm * 32 + mt * 16 + half * 8 + gq;
            int gi = i0 + r;
            if (gi >= iend) continue;
            int orow = (EPI == 2) ? g_perm[gi] : gi;
            size_t rowoff = (size_t)orow * ldc + nb;
            #pragma unroll
            for (int nt = 0; nt < 8; ++nt) {
                int cc = wn * 64 + nt * 8 + 2 * tig;
                float v0 = acc[mt][nt][half * 2 + 0];
                float v1 = acc[mt][nt][half * 2 + 1];
                if (EPI == 0) {
                    *(float2*)&Cf[rowoff + cc] = make_float2(v0, v1);
                } else if (EPI == 2) {
                    const float* bp = bias + (size_t)e * DH + nb + cc;
                    *(float2*)&Cf[rowoff + cc] = make_float2(v0 + bp[0], v1 + bp[1]);
                } else {
                    __nv_bfloat162 o = __floats2bfloat162_rn(v0, v1);
                    *(uint32_t*)&Cb[rowoff + cc] = *(uint32_t*)&o;
                }
            }
        }
    }
}

// ===================== persistent-N fused gate/up GEMM + SwiGLU =============
// grid (NGRP, TMAX); each CTA: resident A (K=128, both streams), loops NPB
// n-blocks of 64 with double-buffered B prefetch.
__global__ void __launch_bounds__(256, 1) mma2(
    const __nv_bfloat16* __restrict__ H2,
    const __nv_bfloat16* __restrict__ Bgw, const __nv_bfloat16* __restrict__ Buw,
    __nv_bfloat16* __restrict__ Y)
{
    extern __shared__ char dsm[];
    uint32_t sb = smem_u32(dsm);
    uint32_t sAg = sb;
    uint32_t sAu = sb + ASTR;
    uint32_t sBg = sb + 2 * ASTR;               // + buf*BSTR
    uint32_t sBu = sb + 2 * ASTR + 2 * BSTR;    // + buf*BSTR

    int ty = blockIdx.y;
    if (ty >= g_ntiles) return;
    int e  = g_tile_e[ty];
    int i0 = g_tile_i0[ty];
    int iend = g_offsets[e + 1];
    int grp = blockIdx.x;
    int tid = threadIdx.x;

    const __nv_bfloat16* Bg = Bgw + (size_t)e * DI * NR;
    const __nv_bfloat16* Bu = Buw + (size_t)e * DI * NR;

    int lane = tid & 31, wid = tid >> 5;
    int wm = wid >> 1, wn = wid & 1;
    int gq = lane >> 2, tig = lane & 3;
    int l7 = lane & 7, lb3 = (lane >> 3) & 1, lb4 = (lane >> 4) & 1;

    uint32_t aOffL = (uint32_t)(wm * 32 + l7 + lb3 * 8) * PITCH + lb4 * 16;
    uint32_t bOffL = (uint32_t)(wn * 32 + l7 + lb4 * 8) * PITCH + lb3 * 16;

    auto rowOf = [&](int r) { int i = i0 + r; return (i < iend) ? i : (iend - 1); };

    auto stageB = [&](int j, int buf) {
        int nb = (grp * NPB + j) * 64;
        #pragma unroll
        for (int l = 0; l < 8; ++l) {
            int idx = tid + l * 256;            // 0..2047
            int st = idx >> 10;
            int rem = idx & 1023;
            int row = rem >> 4;                 // 0..63
            int q = rem & 15;
            int c = q >> 2, ck = q & 3;
            const __nv_bfloat16* src = (st ? Bu : Bg)
                + (size_t)(nb + row) * NR + c * 32 + ck * 8;
            uint32_t dst = (st ? sBu : sBg) + buf * BSTR + c * BCH
                         + row * PITCH + ck * 16;
            CP16(dst, src);
        }
        CPCOMMIT();
    };

    // stage full A (both streams, K=128) + B for j=0
    {
        #pragma unroll
        for (int l = 0; l < 16; ++l) {
            int idx = tid + l * 256;            // 0..4095
            int st = idx >> 11;
            int rem = idx & 2047;
            int row = rem >> 4;                 // 0..127
            int q = rem & 15;
            int c = q >> 2, ck = q & 3;
            const __nv_bfloat16* src = H2 + (size_t)rowOf(row) * 256
                + st * 128 + c * 32 + ck * 8;
            uint32_t dst = (st ? sAu : sAg) + c * ACH + row * PITCH + ck * 16;
            CP16(dst, src);
        }
        CPCOMMIT();
        stageB(0, 0);
    }

    float accG[2][4][4], accU[2][4][4];

    for (int j = 0; j < NPB; ++j) {
        int buf = j & 1;
        CPWAIT(0);
        __syncthreads();
        if (j + 1 < NPB) stageB(j + 1, buf ^ 1);

        #pragma unroll
        for (int mt = 0; mt < 2; ++mt)
            #pragma unroll
            for (int nt = 0; nt < 4; ++nt)
                #pragma unroll
                for (int q = 0; q < 4; ++q) { accG[mt][nt][q] = 0.f; accU[mt][nt][q] = 0.f; }

        #pragma unroll
        for (int c = 0; c < 4; ++c) {
            #pragma unroll
            for (int ks = 0; ks < 2; ++ks) {
                uint32_t ag[2][4], au[2][4], bg[4][2], bu[4][2];
                uint32_t abg = sAg + c * ACH + aOffL + ks * 32;
                uint32_t abu = sAu + c * ACH + aOffL + ks * 32;
                #pragma unroll
                for (int mt = 0; mt < 2; ++mt) {
                    ldsm4(ag[mt], abg + mt * 16 * PITCH);
                    ldsm4(au[mt], abu + mt * 16 * PITCH);
                }
                uint32_t bbg = sBg + buf * BSTR + c * BCH + bOffL + ks * 32;
                uint32_t bbu = sBu + buf * BSTR + c * BCH + bOffL + ks * 32;
                #pragma unroll
                for (int p = 0; p < 2; ++p) {
                    uint32_t qg[4], qu[4];
                    ldsm4(qg, bbg + p * 16 * PITCH);
                    ldsm4(qu, bbu + p * 16 * PITCH);
                    bg[2 * p][0] = qg[0]; bg[2 * p][1] = qg[1];
                    bg[2 * p + 1][0] = qg[2]; bg[2 * p + 1][1] = qg[3];
                    bu[2 * p][0] = qu[0]; bu[2 * p][1] = qu[1];
                    bu[2 * p + 1][0] = qu[2]; bu[2 * p + 1][1] = qu[3];
                }
                #pragma unroll
                for (int mt = 0; mt < 2; ++mt)
                    #pragma unroll
                    for (int nt = 0; nt < 4; ++nt) {
                        mma_bf16(accG[mt][nt], ag[mt], bg[nt]);
                        mma_bf16(accU[mt][nt], au[mt], bu[nt]);
                    }
            }
        }

        // swiglu epilogue for this n-block
        int nb = (grp * NPB + j) * 64;
        #pragma unroll
        for (int mt = 0; mt < 2; ++mt) {
            #pragma unroll
            for (int half = 0; half < 2; ++half) {
                int r = wm * 32 + mt * 16 + half * 8 + gq;
                int gi = i0 + r;
                if (gi >= iend) continue;
                size_t rowoff = (size_t)gi * DI + nb;
                #pragma unroll
                for (int nt = 0; nt < 4; ++nt) {
                    int cc = wn * 32 + nt * 8 + 2 * tig;
                    float g0 = accG[mt][nt][half * 2 + 0];
                    float g1 = accG[mt][nt][half * 2 + 1];
                    float u0 = accU[mt][nt][half * 2 + 0];
                    float u1 = accU[mt][nt][half * 2 + 1];
                    float y0 = u0 * g0 / (1.f + __expf(-g0));
                    float y1 = u1 * g1 / (1.f + __expf(-g1));
                    __nv_bfloat162 o = __floats2bfloat162_rn(y0, y1);
                    *(uint32_t*)&Y[rowoff + cc] = *(uint32_t*)&o;
                }
            }
        }
    }
}

// ===================== split-K reduce -> bf16 ================================
template<int SR>
__global__ void reduce_bf(const float4* __restrict__ P, uint2* __restrict__ O,
                          int n4, size_t stride4)
{
    int i = blockIdx.x * 256 + threadIdx.x;
    if (i >= n4) return;
    float4 s = P[i];
    #pragma unroll
    for (int k = 1; k < SR; ++k) {
        float4 v = P[(size_t)k * stride4 + i];
        s.x += v.x; s.y += v.y; s.z += v.z; s.w += v.w;
    }
    __nv_bfloat162 lo = __floats2bfloat162_rn(s.x, s.y);
    __nv_bfloat162 hi = __floats2bfloat162_rn(s.z, s.w);
    uint2 o; o.x = *(uint32_t*)&lo; o.y = *(uint32_t*)&hi;
    O[i] = o;
}

// ===================== launch ================================================
extern "C" void kernel_launch(void* const* d_in, const int* in_sizes, int n_in,
                              void* d_out, int out_size)
{
    const float* x         = (const float*)d_in[0];
    const int*   eidx      = (const int*)  d_in[1];
    const float* gate_A    = (const float*)d_in[2];
    const float* gate_C    = (const float*)d_in[3];
    const float* gate_B    = (const float*)d_in[4];
    const float* up_A      = (const float*)d_in[5];
    const float* up_C      = (const float*)d_in[6];
    const float* up_B      = (const float*)d_in[7];
    const float* down_A    = (const float*)d_in[8];
    const float* down_C    = (const float*)d_in[9];
    const float* down_B    = (const float*)d_in[10];
    const float* down_bias = (const float*)d_in[11];
    float* out = (float*)d_out;

    __nv_bfloat16 *pXb, *pW1, *pAd, *pBg, *pBu, *pBd, *pCgT, *pCuT, *pCdT,
                  *pH, *pY, *pHd;
    float *pP1, *pP3;
    cudaGetSymbolAddress((void**)&pXb,  g_Xb);
    cudaGetSymbolAddress((void**)&pW1,  g_W1);
    cudaGetSymbolAddress((void**)&pAd,  g_Ad);
    cudaGetSymbolAddress((void**)&pBg,  g_Bg);
    cudaGetSymbolAddress((void**)&pBu,  g_Bu);
    cudaGetSymbolAddress((void**)&pBd,  g_Bd);
    cudaGetSymbolAddress((void**)&pCgT, g_CgT);
    cudaGetSymbolAddress((void**)&pCuT, g_CuT);
    cudaGetSymbolAddress((void**)&pCdT, g_CdT);
    cudaGetSymbolAddress((void**)&pH,   g_H);
    cudaGetSymbolAddress((void**)&pY,   g_Y);
    cudaGetSymbolAddress((void**)&pHd,  g_Hd);
    cudaGetSymbolAddress((void**)&pP1,  g_P1);
    cudaGetSymbolAddress((void**)&pP3,  g_P3);

    const int SM1 = 4 * ABUF + 1024;                  // 41984 (2 CTAs/SM)
    const int SM2 = 2 * ASTR + 4 * BSTR + 256;        // 163  KB + pad (1 CTA/SM)
    const int SMF = 8 * ABUF;                         // 81920
    cudaFuncSetAttribute(mma1<true,  0, 4>, cudaFuncAttributeMaxDynamicSharedMemorySize, SM1);
    cudaFuncSetAttribute(mma1<false, 0, 8>, cudaFuncAttributeMaxDynamicSharedMemorySize, SM1);
    cudaFuncSetAttribute(mma1<false, 2, 1>, cudaFuncAttributeMaxDynamicSharedMemorySize, SM1);
    cudaFuncSetAttribute(mma2, cudaFuncAttributeMaxDynamicSharedMemorySize, SM2);
    cudaFuncSetAttribute(fold_b, cudaFuncAttributeMaxDynamicSharedMemorySize, SMF);

    static bool s_init = false;
    static cudaStream_t s1;
    static cudaEvent_t evFork, evPerm, evFold;
    if (!s_init) {
        cudaStreamCreateWithFlags(&s1, cudaStreamNonBlocking);
        cudaEventCreateWithFlags(&evFork, cudaEventDisableTiming);
        cudaEventCreateWithFlags(&evPerm, cudaEventDisableTiming);
        cudaEventCreateWithFlags(&evFold, cudaEventDisableTiming);
        s_init = true;
    }

    cudaEventRecord(evFork, 0);
    cudaStreamWaitEvent(s1, evFork, 0);

    k_perm<<<1, 1024, 0, s1>>>(eidx);
    cudaEventRecord(evPerm, s1);
    conv_aux<<<dim3(512, 3), 256, 0, s1>>>(
        down_A, gate_C, up_C, down_C, pAd, pCgT, pCuT, pCdT);
    fold_b<<<NE * 104, 256, SMF, s1>>>(
        gate_B, up_B, down_B, pCgT, pCuT, pCdT);
    cudaEventRecord(evFold, s1);

    conv_main<<<dim3(1024, 3), 256>>>(x, gate_A, up_A, pXb, pW1);
    cudaStreamWaitEvent(0, evPerm, 0);

    // K1: H = x_perm @ [gate_A; up_A]^T   (split-K 4, fp32 partials)
    mma1<true, 0, 4><<<dim3(2, TMAX, 4), 256, SM1>>>(
        pXb, DH, pW1, DH, (size_t)256 * DH, DH,
        pP1, 256, (size_t)NT * 256, nullptr);
    reduce_bf<4><<<(NT * 256 / 4 + 255) / 256, 256>>>(
        (const float4*)pP1, (uint2*)pH, NT * 256 / 4, (size_t)NT * 256 / 4);

    cudaStreamWaitEvent(0, evFold, 0);

    // K2: Y = silu(Hg @ Bg'^T) * (Hu @ Bu'^T)   (persistent-N)
    mma2<<<dim3(NGRP, TMAX), 256, SM2>>>(pH, pBg, pBu, pY);

    // K3: Hd = Y @ down_A^T   (split-K 8)
    mma1<false, 0, 8><<<dim3(1, TMAX, 8), 256, SM1>>>(
        pY, DI, pAd, DI, (size_t)NR * DI, DI,
        pP3, NR, (size_t)NT * NR, nullptr);
    reduce_bf<8><<<(NT * NR / 4 + 255) / 256, 256>>>(
        (const float4*)pP3, (uint2*)pHd, NT * NR / 4, (size_t)NT * NR / 4);

    // K4: out[perm[i],:] = Hd @ Bd'^T + bias[e]
    mma1<false, 2, 1><<<dim3(DH / 128, TMAX, 1), 256, SM1>>>(
        pHd, NR, pBd, NR, (size_t)DH * NR, NR,
        out, DH, 0, down_bias);
}

// round 16
// speedup vs baseline: 1.5197x; 1.0181x over previous
#include <cuda_runtime.h>
#include <cuda_bf16.h>
#include <cstdint>

#define NE 8
#define NT 4096
#define DH 2048
#define DI 5632
#define NR 128
#define PITCH 80          // bytes per 32-bf16 smem row (conflict-free for LDSM)
#define ABUF 10240        // 128 rows * 80B
#define BBUF 10240
#define TMAX 40           // max token tiles
#define NGRP 8            // K2 n-groups
#define NPB 11            // n-blocks (of 64) per K2 CTA: 88/8
#define ACH 10240         // A chunk [128][PITCH]
#define BCH 5120          // B chunk [64][PITCH]
#define ASTR (4 * ACH)    // per-stream A (K=128 resident)
#define BSTR (4 * BCH)    // per-stream B buffer
#define NGRP4 8           // K4 n-groups
#define NPB4 4            // n-blocks (of 64) per K4 CTA: 32/8

// ===================== low-level helpers ====================================
__device__ __forceinline__ uint32_t smem_u32(const void* p) {
    uint32_t a;
    asm("{ .reg .u64 t; cvta.to.shared.u64 t, %1; cvt.u32.u64 %0, t; }"
        : "=r"(a) : "l"(p));
    return a;
}
#define CP16(dst, src) \
    asm volatile("cp.async.cg.shared.global [%0], [%1], 16;" \
                 :: "r"(dst), "l"(src) : "memory")
#define CPCOMMIT() asm volatile("cp.async.commit_group;" ::: "memory")
#define CPWAIT(n)  asm volatile("cp.async.wait_group %0;" :: "n"(n) : "memory")

__device__ __forceinline__ void ldsm4(uint32_t r[4], uint32_t addr) {
    asm volatile("ldmatrix.sync.aligned.m8n8.x4.shared.b16 {%0,%1,%2,%3}, [%4];"
        : "=r"(r[0]), "=r"(r[1]), "=r"(r[2]), "=r"(r[3]) : "r"(addr));
}

__device__ __forceinline__ void mma_bf16(
    float c[4], const uint32_t a[4], const uint32_t b[2])
{
    asm volatile(
        "mma.sync.aligned.m16n8k16.row.col.f32.bf16.bf16.f32 "
        "{%0,%1,%2,%3}, {%4,%5,%6,%7}, {%8,%9}, {%0,%1,%2,%3};"
        : "+f"(c[0]), "+f"(c[1]), "+f"(c[2]), "+f"(c[3])
        : "r"(a[0]), "r"(a[1]), "r"(a[2]), "r"(a[3]),
          "r"(b[0]), "r"(b[1]));
}

// ===================== scratch globals ======================================
__device__ int g_offsets[NE + 1];
__device__ int g_perm[NT];
__device__ int g_ntiles;
__device__ int g_tile_e [TMAX + 8];
__device__ int g_tile_i0[TMAX + 8];

__device__ __nv_bfloat16 g_Xb [NT * DH];
__device__ __nv_bfloat16 g_W1 [NE * 256 * DH];
__device__ __nv_bfloat16 g_Ad [NE * NR * DI];
__device__ __nv_bfloat16 g_Bg [NE * DI * NR];
__device__ __nv_bfloat16 g_Bu [NE * DI * NR];
__device__ __nv_bfloat16 g_Bd [NE * DH * NR];
__device__ __nv_bfloat16 g_CgT[NR * NR];
__device__ __nv_bfloat16 g_CuT[NR * NR];
__device__ __nv_bfloat16 g_CdT[NR * NR];
__device__ __nv_bfloat16 g_H  [NT * 256];
__device__ __nv_bfloat16 g_Y  [NT * DI];
__device__ __nv_bfloat16 g_Hd [NT * NR];
__device__ float g_P1[4 * NT * 256];
__device__ float g_P3[8 * NT * NR];

// ===================== single-block permutation + tile table ================
__global__ void k_perm(const int* __restrict__ idx) {
    __shared__ int cnt[NE], off[NE], cur[NE];
    int tid = threadIdx.x;
    if (tid < NE) { cnt[tid] = 0; cur[tid] = 0; }
    __syncthreads();
    for (int t = tid; t < NT; t += 1024) atomicAdd(&cnt[idx[t]], 1);
    __syncthreads();
    if (tid == 0) {
        int s = 0;
        for (int e = 0; e < NE; ++e) { off[e] = s; g_offsets[e] = s; s += cnt[e]; }
        g_offsets[NE] = s;
        int nt2 = 0;
        for (int e = 0; e < NE; ++e)
            for (int i0 = off[e]; i0 < off[e] + cnt[e]; i0 += 128) {
                g_tile_e[nt2] = e; g_tile_i0[nt2] = i0; ++nt2;
            }
        g_ntiles = nt2;
    }
    __syncthreads();
    for (int t = tid; t < NT; t += 1024) {
        int e = idx[t];
        int p = atomicAdd(&cur[e], 1);
        g_perm[off[e] + p] = t;
    }
}

// ===================== conversion kernels ====================================
__device__ __forceinline__ uint2 cvt4(float4 v) {
    __nv_bfloat162 lo = __floats2bfloat162_rn(v.x, v.y);
    __nv_bfloat162 hi = __floats2bfloat162_rn(v.z, v.w);
    uint2 o; o.x = *(uint32_t*)&lo; o.y = *(uint32_t*)&hi;
    return o;
}

#define R0N (NT * DH / 4)
#define RA1 (NE * 128 * DH / 4)
#define RA3 (NE * NR * DI / 4)
#define RCT (NR * NR)

__global__ void conv_main(
    const float* __restrict__ x,
    const float* __restrict__ gate_A, const float* __restrict__ up_A,
    __nv_bfloat16* __restrict__ Xb, __nv_bfloat16* __restrict__ W1)
{
    int r = blockIdx.y;
    int stride = gridDim.x * 256;
    int i0 = blockIdx.x * 256 + threadIdx.x;
    if (r == 0) {
        for (int i = i0; i < R0N; i += stride)
            ((uint2*)Xb)[i] = cvt4(((const float4*)x)[i]);
    } else if (r == 1) {
        for (int i = i0; i < RA1; i += stride) {
            int e = i / (128 * DH / 4), off = i % (128 * DH / 4);
            *(uint2*)(W1 + (size_t)e * 256 * DH + (size_t)off * 4) =
                cvt4(((const float4*)gate_A)[i]);
        }
    } else {
        for (int i = i0; i < RA1; i += stride) {
            int e = i / (128 * DH / 4), off = i % (128 * DH / 4);
            *(uint2*)(W1 + (size_t)e * 256 * DH + (size_t)128 * DH + (size_t)off * 4) =
                cvt4(((const float4*)up_A)[i]);
        }
    }
}

__global__ void conv_aux(
    const float* __restrict__ down_A,
    const float* __restrict__ gate_C, const float* __restrict__ up_C,
    const float* __restrict__ down_C,
    __nv_bfloat16* __restrict__ Ad,
    __nv_bfloat16* __restrict__ CgT, __nv_bfloat16* __restrict__ CuT,
    __nv_bfloat16* __restrict__ CdT)
{
    int r = blockIdx.y;
    int stride = gridDim.x * 256;
    int i0 = blockIdx.x * 256 + threadIdx.x;
    if (r == 0) {
        for (int i = i0; i < RA3; i += stride)
            ((uint2*)Ad)[i] = cvt4(((const float4*)down_A)[i]);
    } else if (r == 1) {
        for (int i = i0; i < RCT; i += stride) {
            int s = i >> 7, rr = i & 127;
            CgT[rr * NR + s] = __float2bfloat16(gate_C[s * NR + rr]);
            CuT[rr * NR + s] = __float2bfloat16(up_C[s * NR + rr]);
        }
    } else {
        for (int i = i0; i < RCT; i += stride) {
            int s = i >> 7, rr = i & 127;
            CdT[rr * NR + s] = __float2bfloat16(down_C[s * NR + rr]);
        }
    }
}

// ===================== fused convert+fold kernel ============================
__global__ void __launch_bounds__(256) fold_b(
    const float* __restrict__ gate_B, const float* __restrict__ up_B,
    const float* __restrict__ down_B,
    const __nv_bfloat16* __restrict__ CgT, const __nv_bfloat16* __restrict__ CuT,
    const __nv_bfloat16* __restrict__ CdT)
{
    extern __shared__ char dsm[];
    uint32_t sb = smem_u32(dsm);
    uint32_t sA = sb, sC = sb + 4 * ABUF;
    char* pA = dsm;
    char* pC = dsm + 4 * ABUF;

    int z = blockIdx.x;
    int e = z / 104, w = z % 104;
    const float* src;
    const __nv_bfloat16* CT;
    __nv_bfloat16* dst;
    int row0;
    if (w < 44)      { src = gate_B + (size_t)e * DI * NR; CT = CgT; dst = g_Bg + (size_t)e * DI * NR; row0 = w * 128; }
    else if (w < 88) { src = up_B   + (size_t)e * DI * NR; CT = CuT; dst = g_Bu + (size_t)e * DI * NR; row0 = (w - 44) * 128; }
    else             { src = down_B + (size_t)e * DH * NR; CT = CdT; dst = g_Bd + (size_t)e * DH * NR; row0 = (w - 88) * 128; }

    int tid = threadIdx.x;

    #pragma unroll
    for (int l = 0; l < 16; ++l) {
        int idx = tid + l * 256;
        int n = idx >> 5;
        int c4 = idx & 31;
        int col = c4 * 4;
        float4 v = *(const float4*)&src[(size_t)(row0 + n) * NR + col];
        int buf = col >> 5;
        int boff = (col & 31) * 2;
        *(uint2*)(pA + buf * ABUF + n * PITCH + boff) = cvt4(v);
    }
    #pragma unroll
    for (int l = 0; l < 8; ++l) {
        int idx = tid + l * 256;
        int r = idx >> 4;
        int ch = idx & 15;
        int scol = ch * 8;
        uint4 v = *(const uint4*)&CT[r * NR + scol];
        int buf = scol >> 5;
        int boff = (scol & 31) * 2;
        *(uint4*)(pC + buf * ABUF + r * PITCH + boff) = v;
    }
    __syncthreads();

    int lane = tid & 31, wid = tid >> 5;
    int wm = wid >> 1, wn = wid & 1;
    int gq = lane >> 2, tig = lane & 3;
    int l7 = lane & 7, lb3 = (lane >> 3) & 1, lb4 = (lane >> 4) & 1;

    uint32_t aLane = sA + (uint32_t)(wm * 32 + l7 + lb3 * 8) * PITCH + lb4 * 16;
    uint32_t bLane = sC + (uint32_t)(wn * 64 + l7 + lb4 * 8) * PITCH + lb3 * 16;

    float acc[2][8][4];
    #pragma unroll
    for (int mt = 0; mt < 2; ++mt)
        #pragma unroll
        for (int nt = 0; nt < 8; ++nt)
            #pragma unroll
            for (int j = 0; j < 4; ++j) acc[mt][nt][j] = 0.f;

    #pragma unroll
    for (int buf = 0; buf < 4; ++buf) {
        #pragma unroll
        for (int ks = 0; ks < 2; ++ks) {
            uint32_t a[2][4], b[8][2];
            uint32_t ab = aLane + buf * ABUF + ks * 32;
            #pragma unroll
            for (int mt = 0; mt < 2; ++mt)
                ldsm4(a[mt], ab + mt * 16 * PITCH);
            uint32_t bb = bLane + buf * ABUF + ks * 32;
            #pragma unroll
            for (int p = 0; p < 4; ++p) {
                uint32_t q[4];
                ldsm4(q, bb + p * 16 * PITCH);
                b[2 * p][0] = q[0]; b[2 * p][1] = q[1];
                b[2 * p + 1][0] = q[2]; b[2 * p + 1][1] = q[3];
            }
            #pragma unroll
            for (int mt = 0; mt < 2; ++mt)
                #pragma unroll
                for (int nt = 0; nt < 8; ++nt)
                    mma_bf16(acc[mt][nt], a[mt], b[nt]);
        }
    }

    #pragma unroll
    for (int mt = 0; mt < 2; ++mt) {
        #pragma unroll
        for (int half = 0; half < 2; ++half) {
            int r = wm * 32 + mt * 16 + half * 8 + gq;
            size_t rowoff = (size_t)(row0 + r) * NR;
            #pragma unroll
            for (int nt = 0; nt < 8; ++nt) {
                int cc = wn * 64 + nt * 8 + 2 * tig;
                __nv_bfloat162 o = __floats2bfloat162_rn(
                    acc[mt][nt][half * 2 + 0], acc[mt][nt][half * 2 + 1]);
                *(uint32_t*)&dst[rowoff + cc] = *(uint32_t*)&o;
            }
        }
    }
}

// ===================== bf16 MMA GEMM (R10 2-stage, tile-table grid) =========
template<bool GATHER, int EPI, int SPLITK>
__global__ void __launch_bounds__(256, 2) mma1(
    const __nv_bfloat16* __restrict__ A, int lda,
    const __nv_bfloat16* __restrict__ B, int ldb, size_t strideBe, int Ktot,
    void* __restrict__ outp, int ldc, size_t splitStride,
    const float* __restrict__ bias)
{
    extern __shared__ char dsm[];
    uint32_t sb = smem_u32(dsm);
    uint32_t sA = sb, sB = sb + 2 * ABUF;
    int* rows = (int*)(dsm + 4 * ABUF);

    int ty = blockIdx.y;
    if (ty >= g_ntiles) return;
    int e  = g_tile_e[ty];
    int i0 = g_tile_i0[ty];
    int iend = g_offsets[e + 1];
    int sk = blockIdx.z;
    int nb = blockIdx.x * 128;
    int tid = threadIdx.x;

    if (tid < 128) {
        int i = i0 + tid; if (i >= iend) i = iend - 1;
        rows[tid] = GATHER ? g_perm[i] : i;
    }
    __syncthreads();

    const __nv_bfloat16* Bp = B + (size_t)e * strideBe;

    int kstep = Ktot / SPLITK;
    int kbeg  = sk * kstep;
    int nk    = kstep / 32;

    int lane = tid & 31, wid = tid >> 5;
    int wm = wid >> 1, wn = wid & 1;
    int gq = lane >> 2, tig = lane & 3;
    int l7 = lane & 7, lb3 = (lane >> 3) & 1, lb4 = (lane >> 4) & 1;

    uint32_t aLane = sA + (uint32_t)(wm * 32 + l7 + lb3 * 8) * PITCH + lb4 * 16;
    uint32_t bLane = sB + (uint32_t)(wn * 64 + l7 + lb4 * 8) * PITCH + lb3 * 16;

    float acc[2][8][4];
    #pragma unroll
    for (int mt = 0; mt < 2; ++mt)
        #pragma unroll
        for (int nt = 0; nt < 8; ++nt)
            #pragma unroll
            for (int j = 0; j < 4; ++j) acc[mt][nt][j] = 0.f;

    // prologue
    {
        #pragma unroll
        for (int l = 0; l < 2; ++l) {
            int idx = tid + l * 256;
            int r = idx >> 2, ch = idx & 3;
            CP16(sA + r * PITCH + ch * 16,
                 A + (size_t)rows[r] * lda + kbeg + ch * 8);
        }
        #pragma unroll
        for (int l = 0; l < 2; ++l) {
            int idx = tid + l * 256;
            int n = idx >> 2, ch = idx & 3;
            CP16(sB + n * PITCH + ch * 16,
                 Bp + (size_t)(nb + n) * ldb + kbeg + ch * 8);
        }
        CPCOMMIT();
    }

    for (int t = 0; t < nk; ++t) {
        int buf = t & 1;
        if (t + 1 < nk) {
            int kb = kbeg + (t + 1) * 32;
            int nbuf = buf ^ 1;
            #pragma unroll
            for (int l = 0; l < 2; ++l) {
                int idx = tid + l * 256;
                int r = idx >> 2, ch = idx & 3;
                CP16(sA + nbuf * ABUF + r * PITCH + ch * 16,
                     A + (size_t)rows[r] * lda + kb + ch * 8);
            }
            #pragma unroll
            for (int l = 0; l < 2; ++l) {
                int idx = tid + l * 256;
                int n = idx >> 2, ch = idx & 3;
                CP16(sB + nbuf * BBUF + n * PITCH + ch * 16,
                     Bp + (size_t)(nb + n) * ldb + kb + ch * 8);
            }
            CPCOMMIT();
            CPWAIT(1);
        } else {
            CPWAIT(0);
        }
        __syncthreads();

        #pragma unroll
        for (int ks = 0; ks < 2; ++ks) {
            uint32_t a[2][4], b[8][2];
            uint32_t ab = aLane + buf * ABUF + ks * 32;
            #pragma unroll
            for (int mt = 0; mt < 2; ++mt)
                ldsm4(a[mt], ab + mt * 16 * PITCH);
            uint32_t bb = bLane + buf * BBUF + ks * 32;
            #pragma unroll
            for (int p = 0; p < 4; ++p) {
                uint32_t q[4];
                ldsm4(q, bb + p * 16 * PITCH);
                b[2 * p][0] = q[0]; b[2 * p][1] = q[1];
                b[2 * p + 1][0] = q[2]; b[2 * p + 1][1] = q[3];
            }
            #pragma unroll
            for (int mt = 0; mt < 2; ++mt)
                #pragma unroll
                for (int nt = 0; nt < 8; ++nt)
                    mma_bf16(acc[mt][nt], a[mt], b[nt]);
        }
        __syncthreads();
    }

    // epilogue
    float* Cf = (float*)outp;
    __nv_bfloat16* Cb = (__nv_bfloat16*)outp;
    if (EPI == 0) Cf += (size_t)sk * splitStride;

    #pragma unroll
    for (int mt = 0; mt < 2; ++mt) {
        #pragma unroll
        for (int half = 0; half < 2; ++half) {
            int r = wm * 32 + mt * 16 + half * 8 + gq;
            int gi = i0 + r;
            if (gi >= iend) continue;
            int orow = (EPI == 2) ? g_perm[gi] : gi;
            size_t rowoff = (size_t)orow * ldc + nb;
            #pragma unroll
            for (int nt = 0; nt < 8; ++nt) {
                int cc = wn * 64 + nt * 8 + 2 * tig;
                float v0 = acc[mt][nt][half * 2 + 0];
                float v1 = acc[mt][nt][half * 2 + 1];
                if (EPI == 0) {
                    *(float2*)&Cf[rowoff + cc] = make_float2(v0, v1);
                } else if (EPI == 2) {
                    const float* bp = bias + (size_t)e * DH + nb + cc;
                    *(float2*)&Cf[rowoff + cc] = make_float2(v0 + bp[0], v1 + bp[1]);
                } else {
                    __nv_bfloat162 o = __floats2bfloat162_rn(v0, v1);
                    *(uint32_t*)&Cb[rowoff + cc] = *(uint32_t*)&o;
                }
            }
        }
    }
}

// ===================== persistent-N fused gate/up GEMM + SwiGLU =============
__global__ void __launch_bounds__(256, 1) mma2(
    const __nv_bfloat16* __restrict__ H2,
    const __nv_bfloat16* __restrict__ Bgw, const __nv_bfloat16* __restrict__ Buw,
    __nv_bfloat16* __restrict__ Y)
{
    extern __shared__ char dsm[];
    uint32_t sb = smem_u32(dsm);
    uint32_t sAg = sb;
    uint32_t sAu = sb + ASTR;
    uint32_t sBg = sb + 2 * ASTR;
    uint32_t sBu = sb + 2 * ASTR + 2 * BSTR;

    int ty = blockIdx.y;
    if (ty >= g_ntiles) return;
    int e  = g_tile_e[ty];
    int i0 = g_tile_i0[ty];
    int iend = g_offsets[e + 1];
    int grp = blockIdx.x;
    int tid = threadIdx.x;

    const __nv_bfloat16* Bg = Bgw + (size_t)e * DI * NR;
    const __nv_bfloat16* Bu = Buw + (size_t)e * DI * NR;

    int lane = tid & 31, wid = tid >> 5;
    int wm = wid >> 1, wn = wid & 1;
    int gq = lane >> 2, tig = lane & 3;
    int l7 = lane & 7, lb3 = (lane >> 3) & 1, lb4 = (lane >> 4) & 1;

    uint32_t aOffL = (uint32_t)(wm * 32 + l7 + lb3 * 8) * PITCH + lb4 * 16;
    uint32_t bOffL = (uint32_t)(wn * 32 + l7 + lb4 * 8) * PITCH + lb3 * 16;

    auto rowOf = [&](int r) { int i = i0 + r; return (i < iend) ? i : (iend - 1); };

    auto stageB = [&](int j, int buf) {
        int nb = (grp * NPB + j) * 64;
        #pragma unroll
        for (int l = 0; l < 8; ++l) {
            int idx = tid + l * 256;
            int st = idx >> 10;
            int rem = idx & 1023;
            int row = rem >> 4;
            int q = rem & 15;
            int c = q >> 2, ck = q & 3;
            const __nv_bfloat16* src = (st ? Bu : Bg)
                + (size_t)(nb + row) * NR + c * 32 + ck * 8;
            uint32_t dst = (st ? sBu : sBg) + buf * BSTR + c * BCH
                         + row * PITCH + ck * 16;
            CP16(dst, src);
        }
        CPCOMMIT();
    };

    {
        #pragma unroll
        for (int l = 0; l < 16; ++l) {
            int idx = tid + l * 256;
            int st = idx >> 11;
            int rem = idx & 2047;
            int row = rem >> 4;
            int q = rem & 15;
            int c = q >> 2, ck = q & 3;
            const __nv_bfloat16* src = H2 + (size_t)rowOf(row) * 256
                + st * 128 + c * 32 + ck * 8;
            uint32_t dst = (st ? sAu : sAg) + c * ACH + row * PITCH + ck * 16;
            CP16(dst, src);
        }
        CPCOMMIT();
        stageB(0, 0);
    }

    float accG[2][4][4], accU[2][4][4];

    for (int j = 0; j < NPB; ++j) {
        int buf = j & 1;
        CPWAIT(0);
        __syncthreads();
        if (j + 1 < NPB) stageB(j + 1, buf ^ 1);

        #pragma unroll
        for (int mt = 0; mt < 2; ++mt)
            #pragma unroll
            for (int nt = 0; nt < 4; ++nt)
                #pragma unroll
                for (int q = 0; q < 4; ++q) { accG[mt][nt][q] = 0.f; accU[mt][nt][q] = 0.f; }

        #pragma unroll
        for (int c = 0; c < 4; ++c) {
            #pragma unroll
            for (int ks = 0; ks < 2; ++ks) {
                uint32_t ag[2][4], au[2][4], bg[4][2], bu[4][2];
                uint32_t abg = sAg + c * ACH + aOffL + ks * 32;
                uint32_t abu = sAu + c * ACH + aOffL + ks * 32;
                #pragma unroll
                for (int mt = 0; mt < 2; ++mt) {
                    ldsm4(ag[mt], abg + mt * 16 * PITCH);
                    ldsm4(au[mt], abu + mt * 16 * PITCH);
                }
                uint32_t bbg = sBg + buf * BSTR + c * BCH + bOffL + ks * 32;
                uint32_t bbu = sBu + buf * BSTR + c * BCH + bOffL + ks * 32;
                #pragma unroll
                for (int p = 0; p < 2; ++p) {
                    uint32_t qg[4], qu[4];
                    ldsm4(qg, bbg + p * 16 * PITCH);
                    ldsm4(qu, bbu + p * 16 * PITCH);
                    bg[2 * p][0] = qg[0]; bg[2 * p][1] = qg[1];
                    bg[2 * p + 1][0] = qg[2]; bg[2 * p + 1][1] = qg[3];
                    bu[2 * p][0] = qu[0]; bu[2 * p][1] = qu[1];
                    bu[2 * p + 1][0] = qu[2]; bu[2 * p + 1][1] = qu[3];
                }
                #pragma unroll
                for (int mt = 0; mt < 2; ++mt)
                    #pragma unroll
                    for (int nt = 0; nt < 4; ++nt) {
                        mma_bf16(accG[mt][nt], ag[mt], bg[nt]);
                        mma_bf16(accU[mt][nt], au[mt], bu[nt]);
                    }
            }
        }

        int nb = (grp * NPB + j) * 64;
        #pragma unroll
        for (int mt = 0; mt < 2; ++mt) {
            #pragma unroll
            for (int half = 0; half < 2; ++half) {
                int r = wm * 32 + mt * 16 + half * 8 + gq;
                int gi = i0 + r;
                if (gi >= iend) continue;
                size_t rowoff = (size_t)gi * DI + nb;
                #pragma unroll
                for (int nt = 0; nt < 4; ++nt) {
                    int cc = wn * 32 + nt * 8 + 2 * tig;
                    float g0 = accG[mt][nt][half * 2 + 0];
                    float g1 = accG[mt][nt][half * 2 + 1];
                    float u0 = accU[mt][nt][half * 2 + 0];
                    float u1 = accU[mt][nt][half * 2 + 1];
                    float y0 = u0 * g0 / (1.f + __expf(-g0));
                    float y1 = u1 * g1 / (1.f + __expf(-g1));
                    __nv_bfloat162 o = __floats2bfloat162_rn(y0, y1);
                    *(uint32_t*)&Y[rowoff + cc] = *(uint32_t*)&o;
                }
            }
        }
    }
}

// ===================== persistent-N down GEMM (K4): bias + scatter ==========
// grid (NGRP4, TMAX); resident A = Hd tile (K=128), loops NPB4 n-blocks of 64.
__global__ void __launch_bounds__(256, 2) mma3(
    const __nv_bfloat16* __restrict__ Hd,
    const __nv_bfloat16* __restrict__ Bdw,
    const float* __restrict__ bias,
    float* __restrict__ out)
{
    extern __shared__ char dsm[];
    uint32_t sb = smem_u32(dsm);
    uint32_t sA = sb;                       // 4*ACH resident
    uint32_t sB = sb + 4 * ACH;             // + buf*BSTR (4*BCH each)

    int ty = blockIdx.y;
    if (ty >= g_ntiles) return;
    int e  = g_tile_e[ty];
    int i0 = g_tile_i0[ty];
    int iend = g_offsets[e + 1];
    int grp = blockIdx.x;
    int tid = threadIdx.x;

    const __nv_bfloat16* Bd = Bdw + (size_t)e * DH * NR;

    int lane = tid & 31, wid = tid >> 5;
    int wm = wid >> 1, wn = wid & 1;
    int gq = lane >> 2, tig = lane & 3;
    int l7 = lane & 7, lb3 = (lane >> 3) & 1, lb4 = (lane >> 4) & 1;

    uint32_t aOffL = (uint32_t)(wm * 32 + l7 + lb3 * 8) * PITCH + lb4 * 16;
    uint32_t bOffL = (uint32_t)(wn * 32 + l7 + lb4 * 8) * PITCH + lb3 * 16;

    auto rowOf = [&](int r) { int i = i0 + r; return (i < iend) ? i : (iend - 1); };

    auto stageB = [&](int j, int buf) {
        int nb = (grp * NPB4 + j) * 64;
        #pragma unroll
        for (int l = 0; l < 4; ++l) {
            int idx = tid + l * 256;            // 0..1023
            int row = idx >> 4;                 // 0..63
            int q = idx & 15;
            int c = q >> 2, ck = q & 3;
            const __nv_bfloat16* src = Bd + (size_t)(nb + row) * NR + c * 32 + ck * 8;
            uint32_t dst = sB + buf * BSTR + c * BCH + row * PITCH + ck * 16;
            CP16(dst, src);
        }
        CPCOMMIT();
    };

    // stage resident A (Hd tile, K=128) + B for j=0
    {
        #pragma unroll
        for (int l = 0; l < 8; ++l) {
            int idx = tid + l * 256;            // 0..2047
            int row = idx >> 4;                 // 0..127
            int q = idx & 15;
            int c = q >> 2, ck = q & 3;
            const __nv_bfloat16* src = Hd + (size_t)rowOf(row) * NR + c * 32 + ck * 8;
            uint32_t dst = sA + c * ACH + row * PITCH + ck * 16;
            CP16(dst, src);
        }
        CPCOMMIT();
        stageB(0, 0);
    }

    float acc[2][4][4];

    for (int j = 0; j < NPB4; ++j) {
        int buf = j & 1;
        CPWAIT(0);
        __syncthreads();
        if (j + 1 < NPB4) stageB(j + 1, buf ^ 1);

        #pragma unroll
        for (int mt = 0; mt < 2; ++mt)
            #pragma unroll
            for (int nt = 0; nt < 4; ++nt)
                #pragma unroll
                for (int q = 0; q < 4; ++q) acc[mt][nt][q] = 0.f;

        #pragma unroll
        for (int c = 0; c < 4; ++c) {
            #pragma unroll
            for (int ks = 0; ks < 2; ++ks) {
                uint32_t a[2][4], b[4][2];
                uint32_t ab = sA + c * ACH + aOffL + ks * 32;
                #pragma unroll
                for (int mt = 0; mt < 2; ++mt)
                    ldsm4(a[mt], ab + mt * 16 * PITCH);
                uint32_t bb = sB + buf * BSTR + c * BCH + bOffL + ks * 32;
                #pragma unroll
                for (int p = 0; p < 2; ++p) {
                    uint32_t q[4];
                    ldsm4(q, bb + p * 16 * PITCH);
                    b[2 * p][0] = q[0]; b[2 * p][1] = q[1];
                    b[2 * p + 1][0] = q[2]; b[2 * p + 1][1] = q[3];
                }
                #pragma unroll
                for (int mt = 0; mt < 2; ++mt)
                    #pragma unroll
                    for (int nt = 0; nt < 4; ++nt)
                        mma_bf16(acc[mt][nt], a[mt], b[nt]);
            }
        }

        int nb = (grp * NPB4 + j) * 64;
        #pragma unroll
        for (int mt = 0; mt < 2; ++mt) {
            #pragma unroll
            for (int half = 0; half < 2; ++half) {
                int r = wm * 32 + mt * 16 + half * 8 + gq;
                int gi = i0 + r;
                if (gi >= iend) continue;
                int orow = g_perm[gi];
                size_t rowoff = (size_t)orow * DH + nb;
                #pragma unroll
                for (int nt = 0; nt < 4; ++nt) {
                    int cc = wn * 32 + nt * 8 + 2 * tig;
                    const float* bp = bias + (size_t)e * DH + nb + cc;
                    float v0 = acc[mt][nt][half * 2 + 0] + bp[0];
                    float v1 = acc[mt][nt][half * 2 + 1] + bp[1];
                    *(float2*)&out[rowoff + cc] = make_float2(v0, v1);
                }
            }
        }
    }
}

// ===================== split-K reduce -> bf16 ================================
template<int SR>
__global__ void reduce_bf(const float4* __restrict__ P, uint2* __restrict__ O,
                          int n4, size_t stride4)
{
    int i = blockIdx.x * 256 + threadIdx.x;
    if (i >= n4) return;
    float4 s = P[i];
    #pragma unroll
    for (int k = 1; k < SR; ++k) {
        float4 v = P[(size_t)k * stride4 + i];
        s.x += v.x; s.y += v.y; s.z += v.z; s.w += v.w;
    }
    __nv_bfloat162 lo = __floats2bfloat162_rn(s.x, s.y);
    __nv_bfloat162 hi = __floats2bfloat162_rn(s.z, s.w);
    uint2 o; o.x = *(uint32_t*)&lo; o.y = *(uint32_t*)&hi;
    O[i] = o;
}

// ===================== launch ================================================
extern "C" void kernel_launch(void* const* d_in, const int* in_sizes, int n_in,
                              void* d_out, int out_size)
{
    const float* x         = (const float*)d_in[0];
    const int*   eidx      = (const int*)  d_in[1];
    const float* gate_A    = (const float*)d_in[2];
    const float* gate_C    = (const float*)d_in[3];
    const float* gate_B    = (const float*)d_in[4];
    const float* up_A      = (const float*)d_in[5];
    const float* up_C      = (const float*)d_in[6];
    const float* up_B      = (const float*)d_in[7];
    const float* down_A    = (const float*)d_in[8];
    const float* down_C    = (const float*)d_in[9];
    const float* down_B    = (const float*)d_in[10];
    const float* down_bias = (const float*)d_in[11];
    float* out = (float*)d_out;

    __nv_bfloat16 *pXb, *pW1, *pAd, *pBg, *pBu, *pBd, *pCgT, *pCuT, *pCdT,
                  *pH, *pY, *pHd;
    float *pP1, *pP3;
    cudaGetSymbolAddress((void**)&pXb,  g_Xb);
    cudaGetSymbolAddress((void**)&pW1,  g_W1);
    cudaGetSymbolAddress((void**)&pAd,  g_Ad);
    cudaGetSymbolAddress((void**)&pBg,  g_Bg);
    cudaGetSymbolAddress((void**)&pBu,  g_Bu);
    cudaGetSymbolAddress((void**)&pBd,  g_Bd);
    cudaGetSymbolAddress((void**)&pCgT, g_CgT);
    cudaGetSymbolAddress((void**)&pCuT, g_CuT);
    cudaGetSymbolAddress((void**)&pCdT, g_CdT);
    cudaGetSymbolAddress((void**)&pH,   g_H);
    cudaGetSymbolAddress((void**)&pY,   g_Y);
    cudaGetSymbolAddress((void**)&pHd,  g_Hd);
    cudaGetSymbolAddress((void**)&pP1,  g_P1);
    cudaGetSymbolAddress((void**)&pP3,  g_P3);

    const int SM1 = 4 * ABUF + 1024;                  // 41984 (2 CTAs/SM)
    const int SM2 = 2 * ASTR + 4 * BSTR + 256;        // ~163 KB (1 CTA/SM)
    const int SM3 = 4 * ACH + 2 * (4 * BCH) + 256;    // 82176 (2 CTAs/SM)
    const int SMF = 8 * ABUF;                         // 81920
    cudaFuncSetAttribute(mma1<true,  0, 4>, cudaFuncAttributeMaxDynamicSharedMemorySize, SM1);
    cudaFuncSetAttribute(mma1<false, 0, 8>, cudaFuncAttributeMaxDynamicSharedMemorySize, SM1);
    cudaFuncSetAttribute(mma2, cudaFuncAttributeMaxDynamicSharedMemorySize, SM2);
    cudaFuncSetAttribute(mma3, cudaFuncAttributeMaxDynamicSharedMemorySize, SM3);
    cudaFuncSetAttribute(fold_b, cudaFuncAttributeMaxDynamicSharedMemorySize, SMF);

    static bool s_init = false;
    static cudaStream_t s1;
    static cudaEvent_t evFork, evPerm, evFold;
    if (!s_init) {
        cudaStreamCreateWithFlags(&s1, cudaStreamNonBlocking);
        cudaEventCreateWithFlags(&evFork, cudaEventDisableTiming);
        cudaEventCreateWithFlags(&evPerm, cudaEventDisableTiming);
        cudaEventCreateWithFlags(&evFold, cudaEventDisableTiming);
        s_init = true;
    }

    cudaEventRecord(evFork, 0);
    cudaStreamWaitEvent(s1, evFork, 0);

    k_perm<<<1, 1024, 0, s1>>>(eidx);
    cudaEventRecord(evPerm, s1);
    conv_aux<<<dim3(512, 3), 256, 0, s1>>>(
        down_A, gate_C, up_C, down_C, pAd, pCgT, pCuT, pCdT);
    fold_b<<<NE * 104, 256, SMF, s1>>>(
        gate_B, up_B, down_B, pCgT, pCuT, pCdT);
    cudaEventRecord(evFold, s1);

    conv_main<<<dim3(1024, 3), 256>>>(x, gate_A, up_A, pXb, pW1);
    cudaStreamWaitEvent(0, evPerm, 0);

    // K1: H = x_perm @ [gate_A; up_A]^T   (split-K 4, fp32 partials)
    mma1<true, 0, 4><<<dim3(2, TMAX, 4), 256, SM1>>>(
        pXb, DH, pW1, DH, (size_t)256 * DH, DH,
        pP1, 256, (size_t)NT * 256, nullptr);
    reduce_bf<4><<<(NT * 256 / 4 + 255) / 256, 256>>>(
        (const float4*)pP1, (uint2*)pH, NT * 256 / 4, (size_t)NT * 256 / 4);

    cudaStreamWaitEvent(0, evFold, 0);

    // K2: Y = silu(Hg @ Bg'^T) * (Hu @ Bu'^T)   (persistent-N)
    mma2<<<dim3(NGRP, TMAX), 256, SM2>>>(pH, pBg, pBu, pY);

    // K3: Hd = Y @ down_A^T   (split-K 8)
    mma1<false, 0, 8><<<dim3(1, TMAX, 8), 256, SM1>>>(
        pY, DI, pAd, DI, (size_t)NR * DI, DI,
        pP3, NR, (size_t)NT * NR, nullptr);
    reduce_bf<8><<<(NT * NR / 4 + 255) / 256, 256>>>(
        (const float4*)pP3, (uint2*)pHd, NT * NR / 4, (size_t)NT * NR / 4);

    // K4: out[perm[i],:] = Hd @ Bd'^T + bias[e]   (persistent-N)
    mma3<<<dim3(NGRP4, TMAX), 256, SM3>>>(pHd, pBd, down_bias, out);
}